// round 4
// baseline (speedup 1.0000x reference)
#include <cuda_runtime.h>
#include <cstdint>

// ---------------------------------------------------------------------------
// Problem constants
// ---------------------------------------------------------------------------
#define BSZ    4
#define CCH    256
#define HH     48
#define WW     48
#define NPIX   2304          // 48*48
#define HEADS  8
#define DH     32
#define INNER  256
#define HID    128
#define LOG2E  1.4426950408889634f
// SCALE * LOG2E folded into q at load
#define QSC    (0.17677669529663687f * 1.4426950408889634f)

// ---------------------------------------------------------------------------
// Scratch (static device globals; no allocations allowed)
// ---------------------------------------------------------------------------
__device__ float g_Wt[4 * 256 * 256];          // 0..2: Wq/Wk/Wv as [c][o]; 3: Wproj as [o][cout]
__device__ float g_luma[BSZ * NPIX];
__device__ float g_biasE[BSZ * NPIX];          // alpha*(pooled_invL - mean)*LOG2E
__device__ float g_h1[BSZ * HID * NPIX];
__device__ float g_hm[BSZ * HID];
__device__ float g_film[BSZ * 6 * 256];        // slots: gq, bqf, gk, bkf, gv, bvf
__device__ float g_qkv[3 * BSZ * HEADS * NPIX * DH];   // [pr][b][h][n][d]
__device__ float g_ao[BSZ * HEADS * NPIX * DH];        // [b][h][n][d]

#define PR_STRIDE (BSZ * HEADS * NPIX * DH)    // 2359296
#define BH_STRIDE (NPIX * DH)                  // 73728
#define B_STRIDE  (HEADS * NPIX * DH)          // 589824

// ---------------------------------------------------------------------------
// Helpers: packed fp32x2 FMA (2x FFMA throughput on sm_103a) + fast exp2
// ---------------------------------------------------------------------------
static __device__ __forceinline__ float2 ffma2(float2 a, float2 b, float2 c) {
    float2 d;
    asm("fma.rn.f32x2 %0, %1, %2, %3;"
        : "=l"(reinterpret_cast<unsigned long long&>(d))
        : "l"(reinterpret_cast<unsigned long long&>(a)),
          "l"(reinterpret_cast<unsigned long long&>(b)),
          "l"(reinterpret_cast<unsigned long long&>(c)));
    return d;
}
static __device__ __forceinline__ float ex2f(float x) {
    float r;
    asm("ex2.approx.f32 %0, %1;" : "=f"(r) : "f"(x));
    return r;
}

// ---------------------------------------------------------------------------
// 1) Weight transposes: Wt[c][o] for q/k/v, Wt[o][cout] for proj
// ---------------------------------------------------------------------------
__global__ void k_transpose(const float* __restrict__ wq, const float* __restrict__ wk,
                            const float* __restrict__ wv, const float* __restrict__ wp) {
    int slot = blockIdx.y, r = blockIdx.x, t = threadIdx.x;
    const float* src = (slot == 0) ? wq : (slot == 1) ? wk : (slot == 2) ? wv : wp;
    g_Wt[slot * 65536 + r * 256 + t] = src[t * 256 + r];
}

// ---------------------------------------------------------------------------
// 2) Luma: y = 0.299R+0.587G+0.114B, per-image min/max normalize
// ---------------------------------------------------------------------------
__global__ void k_luma(const float* __restrict__ rgb) {
    __shared__ float sy[NPIX];
    __shared__ float red[256];
    int b = blockIdx.x, t = threadIdx.x;
    const float* rp = rgb + (size_t)b * 3 * NPIX;
    float lmn = 1e30f, lmx = -1e30f;
#pragma unroll
    for (int k = 0; k < 9; k++) {
        int p = t + k * 256;
        float y = 0.299f * rp[p] + 0.587f * rp[NPIX + p] + 0.114f * rp[2 * NPIX + p];
        sy[p] = y;
        lmn = fminf(lmn, y); lmx = fmaxf(lmx, y);
    }
    red[t] = lmn; __syncthreads();
    for (int s = 128; s > 0; s >>= 1) { if (t < s) red[t] = fminf(red[t], red[t + s]); __syncthreads(); }
    float mn = red[0]; __syncthreads();
    red[t] = lmx; __syncthreads();
    for (int s = 128; s > 0; s >>= 1) { if (t < s) red[t] = fmaxf(red[t], red[t + s]); __syncthreads(); }
    float mx = red[0]; __syncthreads();
    float inv = 1.0f / (mx - mn + 1e-6f);
#pragma unroll
    for (int k = 0; k < 9; k++) {
        int p = t + k * 256;
        g_luma[b * NPIX + p] = (sy[p] - mn) * inv;
    }
}

// ---------------------------------------------------------------------------
// 3) Key bias: invL=1-luma, 3x3 box sum (zero pad)/9, mean-centered, *alpha*LOG2E
// ---------------------------------------------------------------------------
__global__ void k_bias(const float* __restrict__ alpha_p) {
    __shared__ float pli[2500];     // 50x50 zero-padded
    __shared__ float sp[NPIX];
    __shared__ float red[256];
    int b = blockIdx.x, t = threadIdx.x;
    for (int i = t; i < 2500; i += 256) pli[i] = 0.f;
    __syncthreads();
    const float* L = g_luma + b * NPIX;
#pragma unroll
    for (int k = 0; k < 9; k++) {
        int p = t + k * 256;
        pli[(p / 48 + 1) * 50 + (p % 48) + 1] = 1.0f - L[p];
    }
    __syncthreads();
    float lsum = 0.f;
#pragma unroll
    for (int k = 0; k < 9; k++) {
        int p = t + k * 256;
        int bi = (p / 48 + 1) * 50 + (p % 48) + 1;
        float s = pli[bi - 51] + pli[bi - 50] + pli[bi - 49]
                + pli[bi - 1]  + pli[bi]      + pli[bi + 1]
                + pli[bi + 49] + pli[bi + 50] + pli[bi + 51];
        s *= (1.0f / 9.0f);
        sp[p] = s; lsum += s;
    }
    red[t] = lsum; __syncthreads();
    for (int s = 128; s > 0; s >>= 1) { if (t < s) red[t] += red[t + s]; __syncthreads(); }
    float mean = red[0] * (1.0f / (float)NPIX);
    float a = *alpha_p;
#pragma unroll
    for (int k = 0; k < 9; k++) {
        int p = t + k * 256;
        g_biasE[b * NPIX + p] = a * (sp[p] - mean) * LOG2E;
    }
}

// ---------------------------------------------------------------------------
// 4) Conv1: luma[1ch] -> h1[128ch], 3x3 SAME, ReLU
// ---------------------------------------------------------------------------
__global__ void k_conv1(const float* __restrict__ w1, const float* __restrict__ b1) {
    __shared__ float pl[2500];
    int oc = blockIdx.x, b = blockIdx.y, t = threadIdx.x;
    for (int i = t; i < 2500; i += 256) pl[i] = 0.f;
    __syncthreads();
    const float* L = g_luma + b * NPIX;
#pragma unroll
    for (int k = 0; k < 9; k++) {
        int p = t + k * 256;
        pl[(p / 48 + 1) * 50 + (p % 48) + 1] = L[p];
    }
    __syncthreads();
    float w[9];
#pragma unroll
    for (int i = 0; i < 9; i++) w[i] = w1[oc * 9 + i];
    float bb = b1[oc];
    float* dst = g_h1 + ((size_t)(b * HID + oc)) * NPIX;
#pragma unroll
    for (int k = 0; k < 9; k++) {
        int p = t + k * 256;
        int bi = (p / 48 + 1) * 50 + (p % 48) + 1;
        float s = bb
            + pl[bi - 51] * w[0] + pl[bi - 50] * w[1] + pl[bi - 49] * w[2]
            + pl[bi - 1]  * w[3] + pl[bi]      * w[4] + pl[bi + 1]  * w[5]
            + pl[bi + 49] * w[6] + pl[bi + 50] * w[7] + pl[bi + 51] * w[8];
        dst[p] = fmaxf(s, 0.f);
    }
}

// ---------------------------------------------------------------------------
// 5) Conv2 (128->128, 3x3, SAME) + ReLU fused with spatial mean -> hm[b][128]
//    Block: (ocg, b), 4 output channels per block, full spatial plane.
// ---------------------------------------------------------------------------
__global__ __launch_bounds__(256, 1) void k_conv2mean(const float* __restrict__ w2,
                                                      const float* __restrict__ b2) {
    __shared__ float pl[2500];
    __shared__ float wsm[128 * 36];
    int ocg = blockIdx.x, b = blockIdx.y, t = threadIdx.x;

    for (int i = t; i < 128 * 36; i += 256) {
        int ic = i / 36, r = i % 36;
        int oco = r / 9, tp = r % 9;
        wsm[i] = w2[(((ocg * 4 + oco) * 128) + ic) * 9 + tp];
    }
    for (int i = t; i < 2500; i += 256) pl[i] = 0.f;

    int base[9];
#pragma unroll
    for (int k = 0; k < 9; k++) {
        int p = t + k * 256;
        base[k] = (p / 48 + 1) * 50 + (p % 48) + 1;
    }
    float bb[4];
#pragma unroll
    for (int oc = 0; oc < 4; oc++) bb[oc] = b2[ocg * 4 + oc];
    float acc[9][4];
#pragma unroll
    for (int k = 0; k < 9; k++)
#pragma unroll
        for (int oc = 0; oc < 4; oc++) acc[k][oc] = bb[oc];

    for (int ic = 0; ic < 128; ++ic) {
        __syncthreads();
        const float* src = g_h1 + ((size_t)(b * HID + ic)) * NPIX;
#pragma unroll
        for (int k = 0; k < 9; k++) {
            int p = t + k * 256;
            pl[(p / 48 + 1) * 50 + (p % 48) + 1] = src[p];
        }
        __syncthreads();
        float w[36];
#pragma unroll
        for (int i = 0; i < 36; i++) w[i] = wsm[ic * 36 + i];
#pragma unroll
        for (int k = 0; k < 9; k++) {
            int bi = base[k];
            float t0 = pl[bi - 51], t1 = pl[bi - 50], t2 = pl[bi - 49];
            float t3 = pl[bi - 1],  t4 = pl[bi],      t5 = pl[bi + 1];
            float t6 = pl[bi + 49], t7 = pl[bi + 50], t8 = pl[bi + 51];
#pragma unroll
            for (int oc = 0; oc < 4; oc++) {
                acc[k][oc] += t0 * w[oc * 9 + 0] + t1 * w[oc * 9 + 1] + t2 * w[oc * 9 + 2]
                            + t3 * w[oc * 9 + 3] + t4 * w[oc * 9 + 4] + t5 * w[oc * 9 + 5]
                            + t6 * w[oc * 9 + 6] + t7 * w[oc * 9 + 7] + t8 * w[oc * 9 + 8];
            }
        }
    }
    // ReLU + spatial-mean reduction (reuse pl[0..255])
    float part[4];
#pragma unroll
    for (int oc = 0; oc < 4; oc++) {
        float s = 0.f;
#pragma unroll
        for (int k = 0; k < 9; k++) s += fmaxf(acc[k][oc], 0.f);
        part[oc] = s;
    }
    for (int oc = 0; oc < 4; oc++) {
        __syncthreads();
        pl[t] = part[oc];
        __syncthreads();
        for (int s = 128; s > 0; s >>= 1) { if (t < s) pl[t] += pl[t + s]; __syncthreads(); }
        if (t == 0) g_hm[b * HID + ocg * 4 + oc] = pl[0] * (1.0f / (float)NPIX);
    }
}

// ---------------------------------------------------------------------------
// 6) FiLM parameter GEMVs: g_film[b][slot][o] = hm[b] . W[o] + bias[o]
// ---------------------------------------------------------------------------
struct FilmArgs { const float* w[6]; const float* b[6]; };

__global__ void k_film(FilmArgs fa) {
    int s = blockIdx.x, b = blockIdx.y, o = threadIdx.x;
    __shared__ float sh[HID];
    if (threadIdx.x < HID) sh[threadIdx.x] = g_hm[b * HID + threadIdx.x];
    __syncthreads();
    const float* W = fa.w[s] + o * HID;
    float acc = fa.b[s][o];
#pragma unroll 8
    for (int h = 0; h < HID; h++) acc += sh[h] * W[h];
    g_film[(b * 6 + s) * 256 + o] = acc;
}

// ---------------------------------------------------------------------------
// 7) QKV GEMM (+ bias + FiLM), output layout [pr][b][h][n][d]
//    Tile 64(o) x 64(n), K-chunk 16, 256 threads, 4x4 per thread.
// ---------------------------------------------------------------------------
__global__ __launch_bounds__(256) void k_qkv(const float* __restrict__ x,
                                             const float* __restrict__ bq,
                                             const float* __restrict__ bk,
                                             const float* __restrict__ bv) {
    __shared__ float as[16][68];
    __shared__ float bs[16][68];
    int nt = blockIdx.x, mt = blockIdx.y, z = blockIdx.z;
    int pr = z >> 2, b = z & 3;
    int t = threadIdx.x;
    int tx4 = (t & 15) * 4, ty4 = (t >> 4) * 4;
    int n0 = nt * 64, o0 = mt * 64;
    int lr = t >> 4, lc4 = (t & 15) * 4;

    const float* Wt = g_Wt + pr * 65536;
    const float* xb = x + (size_t)b * CCH * NPIX;

    float acc[4][4] = {};
    for (int kk = 0; kk < 256; kk += 16) {
        if (kk) __syncthreads();
        *(float4*)&as[lr][lc4] = *(const float4*)&Wt[(kk + lr) * 256 + o0 + lc4];
        *(float4*)&bs[lr][lc4] = *(const float4*)&xb[(size_t)(kk + lr) * NPIX + n0 + lc4];
        __syncthreads();
#pragma unroll
        for (int k = 0; k < 16; k++) {
            float4 a4 = *(const float4*)&as[k][ty4];
            float4 b4 = *(const float4*)&bs[k][tx4];
            float av[4] = { a4.x, a4.y, a4.z, a4.w };
            float bvv[4] = { b4.x, b4.y, b4.z, b4.w };
#pragma unroll
            for (int i = 0; i < 4; i++)
#pragma unroll
                for (int j = 0; j < 4; j++)
                    acc[i][j] += av[i] * bvv[j];
        }
    }
    // epilogue: FiLM(g*(t+bias)+beta), store float4 over d
    const float* fg  = g_film + (b * 6 + 2 * pr) * 256;
    const float* fb2 = g_film + (b * 6 + 2 * pr + 1) * 256;
    const float* bias = (pr == 0) ? bq : (pr == 1) ? bk : bv;
    int ob = o0 + ty4;
    int h = ob >> 5, d0 = ob & 31;
    float gg[4], be[4], bi[4];
#pragma unroll
    for (int i = 0; i < 4; i++) { gg[i] = fg[ob + i]; be[i] = fb2[ob + i]; bi[i] = bias[ob + i]; }
    float* outb = g_qkv + (size_t)pr * PR_STRIDE + (size_t)b * B_STRIDE;
#pragma unroll
    for (int j = 0; j < 4; j++) {
        int n = n0 + tx4 + j;
        float4 v;
        v.x = gg[0] * (acc[0][j] + bi[0]) + be[0];
        v.y = gg[1] * (acc[1][j] + bi[1]) + be[1];
        v.z = gg[2] * (acc[2][j] + bi[2]) + be[2];
        v.w = gg[3] * (acc[3][j] + bi[3]) + be[3];
        *(float4*)&outb[((size_t)h * NPIX + n) * DH + d0] = v;
    }
}

// ---------------------------------------------------------------------------
// 8) Attention: flash-style streaming softmax, f32x2 packed math throughout.
//    grid (18 q-tiles, 32 bh), block 128 threads, 1 query per thread.
// ---------------------------------------------------------------------------
__global__ __launch_bounds__(128) void k_attn() {
    __shared__ float ks[64 * 32];
    __shared__ float vs[64 * 32];
    __shared__ float bsm[64];
    int t = threadIdx.x;
    int bh = blockIdx.y;
    int b = bh >> 3;
    int qi = blockIdx.x * 128 + t;

    const float* Qb = g_qkv + (size_t)bh * BH_STRIDE;
    const float* Kb = g_qkv + (size_t)PR_STRIDE + (size_t)bh * BH_STRIDE;
    const float* Vb = g_qkv + (size_t)2 * PR_STRIDE + (size_t)bh * BH_STRIDE;
    const float* bE = g_biasE + b * NPIX;

    float2 q2[16];
    {
        const float4* qp = (const float4*)(Qb + (size_t)qi * DH);
#pragma unroll
        for (int i = 0; i < 8; i++) {
            float4 v = qp[i];
            q2[2 * i]     = make_float2(v.x * QSC, v.y * QSC);
            q2[2 * i + 1] = make_float2(v.z * QSC, v.w * QSC);
        }
    }
    float2 o2[16];
#pragma unroll
    for (int i = 0; i < 16; i++) o2[i] = make_float2(0.f, 0.f);
    float m = -1e30f, l = 0.f;

    for (int nk = 0; nk < 36; ++nk) {
        const float4* Kg = (const float4*)Kb + nk * 512;
        const float4* Vg = (const float4*)Vb + nk * 512;
#pragma unroll
        for (int i = t; i < 512; i += 128) {
            ((float4*)ks)[i] = Kg[i];
            ((float4*)vs)[i] = Vg[i];
        }
        if (t < 64) bsm[t] = bE[nk * 64 + t];
        __syncthreads();

#pragma unroll 4
        for (int j = 0; j < 64; ++j) {
            const float2* kr = (const float2*)(ks + j * 32);
            float2 sa = make_float2(0.f, 0.f), sb = sa;
#pragma unroll
            for (int i = 0; i < 16; i += 2) {
                sa = ffma2(q2[i],     kr[i],     sa);
                sb = ffma2(q2[i + 1], kr[i + 1], sb);
            }
            float se = sa.x + sa.y + sb.x + sb.y + bsm[j];
            const float2* vr = (const float2*)(vs + j * 32);
            if (se > m) {
                float corr = ex2f(m - se);
                m = se;
                l = l * corr + 1.0f;
                float2 cc = make_float2(corr, corr);
#pragma unroll
                for (int i = 0; i < 16; i++) o2[i] = ffma2(cc, o2[i], vr[i]);
            } else {
                float p = ex2f(se - m);
                l += p;
                float2 pp = make_float2(p, p);
#pragma unroll
                for (int i = 0; i < 16; i++) o2[i] = ffma2(pp, vr[i], o2[i]);
            }
        }
        __syncthreads();
    }
    float inv = 1.0f / l;
    float* AOb = g_ao + (size_t)bh * BH_STRIDE + (size_t)qi * DH;
#pragma unroll
    for (int i = 0; i < 8; i++) {
        float4 v;
        v.x = o2[2 * i].x * inv;     v.y = o2[2 * i].y * inv;
        v.z = o2[2 * i + 1].x * inv; v.w = o2[2 * i + 1].y * inv;
        ((float4*)AOb)[i] = v;
    }
}

// ---------------------------------------------------------------------------
// 9) Output projection GEMM: out[b][c][n] = Wproj @ ao + bproj
// ---------------------------------------------------------------------------
__global__ __launch_bounds__(256) void k_proj(const float* __restrict__ bproj,
                                              float* __restrict__ out) {
    __shared__ float as[16][68];
    __shared__ float bs[16][68];
    int nt = blockIdx.x, mt = blockIdx.y, b = blockIdx.z;
    int t = threadIdx.x;
    int tx4 = (t & 15) * 4, ty4 = (t >> 4) * 4;
    int n0 = nt * 64, m0 = mt * 64;
    int lr = t >> 4, lc4 = (t & 15) * 4;

    const float* Wt = g_Wt + 3 * 65536;
    const float* AOb = g_ao + (size_t)b * B_STRIDE;

    float acc[4][4] = {};
    for (int kk = 0; kk < 256; kk += 16) {
        if (kk) __syncthreads();
        *(float4*)&as[lr][lc4] = *(const float4*)&Wt[(kk + lr) * 256 + m0 + lc4];
#pragma unroll
        for (int i = 0; i < 4; i++) {
            int lin = t + i * 256;
            int orow = lin & 15, nc = lin >> 4;
            int o = kk + orow;
            bs[orow][nc] = AOb[((size_t)(o >> 5) * NPIX + n0 + nc) * DH + (o & 31)];
        }
        __syncthreads();
#pragma unroll
        for (int k = 0; k < 16; k++) {
            float4 a4 = *(const float4*)&as[k][ty4];
            float4 b4 = *(const float4*)&bs[k][tx4];
            float av[4] = { a4.x, a4.y, a4.z, a4.w };
            float bvv[4] = { b4.x, b4.y, b4.z, b4.w };
#pragma unroll
            for (int i = 0; i < 4; i++)
#pragma unroll
                for (int j = 0; j < 4; j++)
                    acc[i][j] += av[i] * bvv[j];
        }
    }
#pragma unroll
    for (int i = 0; i < 4; i++) {
        int mrow = m0 + ty4 + i;
        float bp = bproj[mrow];
        float4 v = make_float4(acc[i][0] + bp, acc[i][1] + bp, acc[i][2] + bp, acc[i][3] + bp);
        *(float4*)&out[((size_t)b * CCH + mrow) * NPIX + n0 + tx4] = v;
    }
}

// ---------------------------------------------------------------------------
// launch
// ---------------------------------------------------------------------------
extern "C" void kernel_launch(void* const* d_in, const int* in_sizes, int n_in,
                              void* d_out, int out_size) {
    const float* x     = (const float*)d_in[0];
    const float* rgb   = (const float*)d_in[1];
    const float* wq    = (const float*)d_in[2];
    const float* bq    = (const float*)d_in[3];
    const float* wk    = (const float*)d_in[4];
    const float* bk    = (const float*)d_in[5];
    const float* wv    = (const float*)d_in[6];
    const float* bv    = (const float*)d_in[7];
    const float* wproj = (const float*)d_in[8];
    const float* bproj = (const float*)d_in[9];
    const float* c1w   = (const float*)d_in[10];
    const float* c1b   = (const float*)d_in[11];
    const float* c2w   = (const float*)d_in[12];
    const float* c2b   = (const float*)d_in[13];
    const float* alpha = (const float*)d_in[26];

    FilmArgs fa;
    fa.w[0] = (const float*)d_in[14]; fa.b[0] = (const float*)d_in[15];
    fa.w[1] = (const float*)d_in[16]; fa.b[1] = (const float*)d_in[17];
    fa.w[2] = (const float*)d_in[18]; fa.b[2] = (const float*)d_in[19];
    fa.w[3] = (const float*)d_in[20]; fa.b[3] = (const float*)d_in[21];
    fa.w[4] = (const float*)d_in[22]; fa.b[4] = (const float*)d_in[23];
    fa.w[5] = (const float*)d_in[24]; fa.b[5] = (const float*)d_in[25];

    k_transpose<<<dim3(256, 4), 256>>>(wq, wk, wv, wproj);
    k_luma<<<BSZ, 256>>>(rgb);
    k_bias<<<BSZ, 256>>>(alpha);
    k_conv1<<<dim3(HID, BSZ), 256>>>(c1w, c1b);
    k_conv2mean<<<dim3(HID / 4, BSZ), 256>>>(c2w, c2b);
    k_film<<<dim3(6, BSZ), 256>>>(fa);
    k_qkv<<<dim3(36, 4, 12), 256>>>(x, bq, bk, bv);
    k_attn<<<dim3(18, 32), 128>>>();
    k_proj<<<dim3(36, 4, 4), 256>>>(bproj, (float*)d_out);
}

// round 7
// speedup vs baseline: 1.0245x; 1.0245x over previous
#include <cuda_runtime.h>
#include <cstdint>

// ---------------------------------------------------------------------------
// Problem constants
// ---------------------------------------------------------------------------
#define BSZ    4
#define CCH    256
#define HH     48
#define WW     48
#define NPIX   2304          // 48*48
#define HEADS  8
#define DH     32
#define INNER  256
#define HID    128
#define LOG2E  1.4426950408889634f
// SCALE * LOG2E folded into q at load
#define QSC    (0.17677669529663687f * 1.4426950408889634f)

// ---------------------------------------------------------------------------
// Scratch (static device globals; no allocations allowed)
// ---------------------------------------------------------------------------
__device__ float g_Wt[4 * 256 * 256];          // 0..2: Wq/Wk/Wv as [c][o]; 3: Wproj as [o][cout]
__device__ float g_luma[BSZ * NPIX];
__device__ float g_biasE[BSZ * NPIX];          // alpha*(pooled_invL - mean)*LOG2E
__device__ float g_h1[BSZ * HID * NPIX];
__device__ float g_hm[BSZ * HID];
__device__ float g_film[BSZ * 6 * 256];        // slots: gq, bqf, gk, bkf, gv, bvf
__device__ float g_qkv[3 * BSZ * HEADS * NPIX * DH];   // [pr][b][h][n][d]
__device__ float g_ao[BSZ * HEADS * NPIX * DH];        // [b][h][n][d]

#define PR_STRIDE (BSZ * HEADS * NPIX * DH)    // 2359296
#define BH_STRIDE (NPIX * DH)                  // 73728
#define B_STRIDE  (HEADS * NPIX * DH)          // 589824

// ---------------------------------------------------------------------------
// Helpers: packed fp32x2 FMA (2x FFMA throughput on sm_103a) + fast exp2
// ---------------------------------------------------------------------------
static __device__ __forceinline__ float2 ffma2(float2 a, float2 b, float2 c) {
    float2 d;
    asm("fma.rn.f32x2 %0, %1, %2, %3;"
        : "=l"(reinterpret_cast<unsigned long long&>(d))
        : "l"(reinterpret_cast<unsigned long long&>(a)),
          "l"(reinterpret_cast<unsigned long long&>(b)),
          "l"(reinterpret_cast<unsigned long long&>(c)));
    return d;
}
static __device__ __forceinline__ float ex2f(float x) {
    float r;
    asm("ex2.approx.f32 %0, %1;" : "=f"(r) : "f"(x));
    return r;
}

// ---------------------------------------------------------------------------
// 1) Weight transposes: Wt[c][o] for q/k/v, Wt[o][cout] for proj
// ---------------------------------------------------------------------------
__global__ void k_transpose(const float* __restrict__ wq, const float* __restrict__ wk,
                            const float* __restrict__ wv, const float* __restrict__ wp) {
    int slot = blockIdx.y, r = blockIdx.x, t = threadIdx.x;
    const float* src = (slot == 0) ? wq : (slot == 1) ? wk : (slot == 2) ? wv : wp;
    g_Wt[slot * 65536 + r * 256 + t] = src[t * 256 + r];
}

// ---------------------------------------------------------------------------
// 2) Luma (min/max normalized) + key bias, fused. grid(BSZ), block 256.
// ---------------------------------------------------------------------------
__global__ void k_lumabias(const float* __restrict__ rgb, const float* __restrict__ alpha_p) {
    __shared__ float sy[NPIX];
    __shared__ float pli[2500];     // 50x50 zero-padded inverse-luma
    __shared__ float red[256];
    int b = blockIdx.x, t = threadIdx.x;
    const float* rp = rgb + (size_t)b * 3 * NPIX;
    float lmn = 1e30f, lmx = -1e30f;
#pragma unroll
    for (int k = 0; k < 9; k++) {
        int p = t + k * 256;
        float y = 0.299f * rp[p] + 0.587f * rp[NPIX + p] + 0.114f * rp[2 * NPIX + p];
        sy[p] = y;
        lmn = fminf(lmn, y); lmx = fmaxf(lmx, y);
    }
    red[t] = lmn; __syncthreads();
    for (int s = 128; s > 0; s >>= 1) { if (t < s) red[t] = fminf(red[t], red[t + s]); __syncthreads(); }
    float mn = red[0]; __syncthreads();
    red[t] = lmx; __syncthreads();
    for (int s = 128; s > 0; s >>= 1) { if (t < s) red[t] = fmaxf(red[t], red[t + s]); __syncthreads(); }
    float mx = red[0]; __syncthreads();
    float inv = 1.0f / (mx - mn + 1e-6f);

    for (int i = t; i < 2500; i += 256) pli[i] = 0.f;
    __syncthreads();
#pragma unroll
    for (int k = 0; k < 9; k++) {
        int p = t + k * 256;
        float ln = (sy[p] - mn) * inv;
        g_luma[b * NPIX + p] = ln;
        pli[(p / 48 + 1) * 50 + (p % 48) + 1] = 1.0f - ln;
    }
    __syncthreads();
    float lsum = 0.f;
#pragma unroll
    for (int k = 0; k < 9; k++) {
        int p = t + k * 256;
        int bi = (p / 48 + 1) * 50 + (p % 48) + 1;
        float s = pli[bi - 51] + pli[bi - 50] + pli[bi - 49]
                + pli[bi - 1]  + pli[bi]      + pli[bi + 1]
                + pli[bi + 49] + pli[bi + 50] + pli[bi + 51];
        s *= (1.0f / 9.0f);
        sy[p] = s; lsum += s;
    }
    red[t] = lsum; __syncthreads();
    for (int s = 128; s > 0; s >>= 1) { if (t < s) red[t] += red[t + s]; __syncthreads(); }
    float mean = red[0] * (1.0f / (float)NPIX);
    float a = *alpha_p;
#pragma unroll
    for (int k = 0; k < 9; k++) {
        int p = t + k * 256;
        g_biasE[b * NPIX + p] = a * (sy[p] - mean) * LOG2E;
    }
}

// ---------------------------------------------------------------------------
// 4) Conv1: luma[1ch] -> h1[128ch], 3x3 SAME, ReLU
// ---------------------------------------------------------------------------
__global__ void k_conv1(const float* __restrict__ w1, const float* __restrict__ b1) {
    __shared__ float pl[2500];
    int oc = blockIdx.x, b = blockIdx.y, t = threadIdx.x;
    for (int i = t; i < 2500; i += 256) pl[i] = 0.f;
    __syncthreads();
    const float* L = g_luma + b * NPIX;
#pragma unroll
    for (int k = 0; k < 9; k++) {
        int p = t + k * 256;
        pl[(p / 48 + 1) * 50 + (p % 48) + 1] = L[p];
    }
    __syncthreads();
    float w[9];
#pragma unroll
    for (int i = 0; i < 9; i++) w[i] = w1[oc * 9 + i];
    float bb = b1[oc];
    float* dst = g_h1 + ((size_t)(b * HID + oc)) * NPIX;
#pragma unroll
    for (int k = 0; k < 9; k++) {
        int p = t + k * 256;
        int bi = (p / 48 + 1) * 50 + (p % 48) + 1;
        float s = bb
            + pl[bi - 51] * w[0] + pl[bi - 50] * w[1] + pl[bi - 49] * w[2]
            + pl[bi - 1]  * w[3] + pl[bi]      * w[4] + pl[bi + 1]  * w[5]
            + pl[bi + 49] * w[6] + pl[bi + 50] * w[7] + pl[bi + 51] * w[8];
        dst[p] = fmaxf(s, 0.f);
    }
}

// ---------------------------------------------------------------------------
// 5) Conv2 (128->128, 3x3, SAME) + ReLU fused with spatial mean -> hm[b][128]
//    4 output channels per block packed as f32x2 pairs.
// ---------------------------------------------------------------------------
__global__ __launch_bounds__(256, 1) void k_conv2mean(const float* __restrict__ w2,
                                                      const float* __restrict__ b2) {
    __shared__ float pl[2500];
    __shared__ float wsm[128 * 36];   // layout [ic][tap][oc], oc fastest (float4-aligned)
    int ocg = blockIdx.x, b = blockIdx.y, t = threadIdx.x;

    for (int i = t; i < 128 * 36; i += 256) {
        int ic = i / 36, r = i % 36;
        int tap = r / 4, oc = r % 4;
        wsm[i] = w2[(((ocg * 4 + oc) * 128) + ic) * 9 + tap];
    }
    for (int i = t; i < 2500; i += 256) pl[i] = 0.f;

    int base[9];
#pragma unroll
    for (int k = 0; k < 9; k++) {
        int p = t + k * 256;
        base[k] = (p / 48 + 1) * 50 + (p % 48) + 1;
    }
    float2 bb0 = make_float2(b2[ocg * 4 + 0], b2[ocg * 4 + 1]);
    float2 bb1 = make_float2(b2[ocg * 4 + 2], b2[ocg * 4 + 3]);
    float2 acc2[9][2];
#pragma unroll
    for (int k = 0; k < 9; k++) { acc2[k][0] = bb0; acc2[k][1] = bb1; }

    const int off[9] = { -51, -50, -49, -1, 0, 1, 49, 50, 51 };

    for (int ic = 0; ic < 128; ++ic) {
        __syncthreads();
        const float* src = g_h1 + ((size_t)(b * HID + ic)) * NPIX;
#pragma unroll
        for (int k = 0; k < 9; k++) {
            int p = t + k * 256;
            pl[(p / 48 + 1) * 50 + (p % 48) + 1] = src[p];
        }
        __syncthreads();
        float4 wv[9];
#pragma unroll
        for (int tap = 0; tap < 9; tap++) wv[tap] = *(const float4*)&wsm[(ic * 9 + tap) * 4];
#pragma unroll
        for (int k = 0; k < 9; k++) {
            int bi = base[k];
            float2 a0 = acc2[k][0], a1 = acc2[k][1];
#pragma unroll
            for (int tap = 0; tap < 9; tap++) {
                float tv = pl[bi + off[tap]];
                float2 tt = make_float2(tv, tv);
                a0 = ffma2(tt, make_float2(wv[tap].x, wv[tap].y), a0);
                a1 = ffma2(tt, make_float2(wv[tap].z, wv[tap].w), a1);
            }
            acc2[k][0] = a0; acc2[k][1] = a1;
        }
    }
    // ReLU + spatial-mean reduction (reuse pl[0..255])
    float part[4];
#pragma unroll
    for (int oc = 0; oc < 4; oc++) {
        float s = 0.f;
#pragma unroll
        for (int k = 0; k < 9; k++) {
            float v = (oc == 0) ? acc2[k][0].x : (oc == 1) ? acc2[k][0].y
                    : (oc == 2) ? acc2[k][1].x : acc2[k][1].y;
            s += fmaxf(v, 0.f);
        }
        part[oc] = s;
    }
    for (int oc = 0; oc < 4; oc++) {
        __syncthreads();
        pl[t] = part[oc];
        __syncthreads();
        for (int s = 128; s > 0; s >>= 1) { if (t < s) pl[t] += pl[t + s]; __syncthreads(); }
        if (t == 0) g_hm[b * HID + ocg * 4 + oc] = pl[0] * (1.0f / (float)NPIX);
    }
}

// ---------------------------------------------------------------------------
// 6) FiLM parameter GEMVs
// ---------------------------------------------------------------------------
struct FilmArgs { const float* w[6]; const float* b[6]; };

__global__ void k_film(FilmArgs fa) {
    int s = blockIdx.x, b = blockIdx.y, o = threadIdx.x;
    __shared__ float sh[HID];
    if (threadIdx.x < HID) sh[threadIdx.x] = g_hm[b * HID + threadIdx.x];
    __syncthreads();
    const float* W = fa.w[s] + o * HID;
    float acc = fa.b[s][o];
#pragma unroll 8
    for (int h = 0; h < HID; h++) acc += sh[h] * W[h];
    g_film[(b * 6 + s) * 256 + o] = acc;
}

// ---------------------------------------------------------------------------
// 7) QKV GEMM (+ bias + FiLM), output [pr][b][h][n][d]; f32x2 inner product
// ---------------------------------------------------------------------------
__global__ __launch_bounds__(256) void k_qkv(const float* __restrict__ x,
                                             const float* __restrict__ bq,
                                             const float* __restrict__ bk,
                                             const float* __restrict__ bv) {
    __shared__ float as[16][68];
    __shared__ float bs[16][68];
    int nt = blockIdx.x, mt = blockIdx.y, z = blockIdx.z;
    int pr = z >> 2, b = z & 3;
    int t = threadIdx.x;
    int tx4 = (t & 15) * 4, ty4 = (t >> 4) * 4;
    int n0 = nt * 64, o0 = mt * 64;
    int lr = t >> 4, lc4 = (t & 15) * 4;

    const float* Wt = g_Wt + pr * 65536;
    const float* xb = x + (size_t)b * CCH * NPIX;

    float2 acc2[4][2];
#pragma unroll
    for (int i = 0; i < 4; i++) { acc2[i][0] = make_float2(0.f, 0.f); acc2[i][1] = make_float2(0.f, 0.f); }
    for (int kk = 0; kk < 256; kk += 16) {
        if (kk) __syncthreads();
        *(float4*)&as[lr][lc4] = *(const float4*)&Wt[(kk + lr) * 256 + o0 + lc4];
        *(float4*)&bs[lr][lc4] = *(const float4*)&xb[(size_t)(kk + lr) * NPIX + n0 + lc4];
        __syncthreads();
#pragma unroll
        for (int k = 0; k < 16; k++) {
            float4 a4 = *(const float4*)&as[k][ty4];
            float4 b4 = *(const float4*)&bs[k][tx4];
            float2 b01 = make_float2(b4.x, b4.y), b23 = make_float2(b4.z, b4.w);
            float av[4] = { a4.x, a4.y, a4.z, a4.w };
#pragma unroll
            for (int i = 0; i < 4; i++) {
                float2 ai = make_float2(av[i], av[i]);
                acc2[i][0] = ffma2(ai, b01, acc2[i][0]);
                acc2[i][1] = ffma2(ai, b23, acc2[i][1]);
            }
        }
    }
    float acc[4][4];
#pragma unroll
    for (int i = 0; i < 4; i++) {
        acc[i][0] = acc2[i][0].x; acc[i][1] = acc2[i][0].y;
        acc[i][2] = acc2[i][1].x; acc[i][3] = acc2[i][1].y;
    }
    // epilogue: FiLM(g*(t+bias)+beta), store float4 over d
    const float* fg  = g_film + (b * 6 + 2 * pr) * 256;
    const float* fb2 = g_film + (b * 6 + 2 * pr + 1) * 256;
    const float* bias = (pr == 0) ? bq : (pr == 1) ? bk : bv;
    int ob = o0 + ty4;
    int h = ob >> 5, d0 = ob & 31;
    float gg[4], be[4], bi[4];
#pragma unroll
    for (int i = 0; i < 4; i++) { gg[i] = fg[ob + i]; be[i] = fb2[ob + i]; bi[i] = bias[ob + i]; }
    float* outb = g_qkv + (size_t)pr * PR_STRIDE + (size_t)b * B_STRIDE;
#pragma unroll
    for (int j = 0; j < 4; j++) {
        int n = n0 + tx4 + j;
        float4 v;
        v.x = gg[0] * (acc[0][j] + bi[0]) + be[0];
        v.y = gg[1] * (acc[1][j] + bi[1]) + be[1];
        v.z = gg[2] * (acc[2][j] + bi[2]) + be[2];
        v.w = gg[3] * (acc[3][j] + bi[3]) + be[3];
        *(float4*)&outb[((size_t)h * NPIX + n) * DH + d0] = v;
    }
}

// ---------------------------------------------------------------------------
// 8) Attention: flash-style streaming softmax, 2 queries/thread, f32x2 math,
//    LDS.128 broadcast K/V reads. grid (9 q-tiles, 32 bh), block 128.
// ---------------------------------------------------------------------------
__global__ __launch_bounds__(128) void k_attn() {
    __shared__ float4 ks[512];     // 64 keys x 32 d
    __shared__ float4 vs[512];
    __shared__ float bsm[64];
    int t = threadIdx.x;
    int bh = blockIdx.y;
    int b = bh >> 3;
    int q0 = blockIdx.x * 256 + t;          // second query = q0 + 128

    const float* Qb = g_qkv + (size_t)bh * BH_STRIDE;
    const float* Kb = g_qkv + (size_t)PR_STRIDE + (size_t)bh * BH_STRIDE;
    const float* Vb = g_qkv + (size_t)2 * PR_STRIDE + (size_t)bh * BH_STRIDE;
    const float* bE = g_biasE + b * NPIX;

    float4 qa[8], qb[8];
    {
        const float4* qpa = (const float4*)(Qb + (size_t)q0 * DH);
        const float4* qpb = (const float4*)(Qb + (size_t)(q0 + 128) * DH);
#pragma unroll
        for (int i = 0; i < 8; i++) {
            float4 va = qpa[i], vb = qpb[i];
            qa[i] = make_float4(va.x * QSC, va.y * QSC, va.z * QSC, va.w * QSC);
            qb[i] = make_float4(vb.x * QSC, vb.y * QSC, vb.z * QSC, vb.w * QSC);
        }
    }
    float2 oa[16], ob[16];
#pragma unroll
    for (int i = 0; i < 16; i++) { oa[i] = make_float2(0.f, 0.f); ob[i] = make_float2(0.f, 0.f); }
    float ma = -1e30f, la = 0.f, mb = -1e30f, lb = 0.f;

    for (int nk = 0; nk < 36; ++nk) {
        const float4* Kg = (const float4*)Kb + nk * 512;
        const float4* Vg = (const float4*)Vb + nk * 512;
#pragma unroll
        for (int i = t; i < 512; i += 128) {
            ks[i] = Kg[i];
            vs[i] = Vg[i];
        }
        if (t < 64) bsm[t] = bE[nk * 64 + t];
        __syncthreads();

#pragma unroll 2
        for (int j = 0; j < 64; ++j) {
            const float4* kr = &ks[j * 8];
            float4 k0 = kr[0], k1 = kr[1], k2 = kr[2], k3 = kr[3];
            float4 k4 = kr[4], k5 = kr[5], k6 = kr[6], k7 = kr[7];
            float bj = bsm[j];

            float2 s0 = make_float2(0.f, 0.f), s1 = s0, u0 = s0, u1 = s0;
#pragma unroll
            for (int i = 0; i < 8; i++) {
                float4 kv = (i == 0) ? k0 : (i == 1) ? k1 : (i == 2) ? k2 : (i == 3) ? k3
                          : (i == 4) ? k4 : (i == 5) ? k5 : (i == 6) ? k6 : k7;
                float2 klo = make_float2(kv.x, kv.y), khi = make_float2(kv.z, kv.w);
                s0 = ffma2(make_float2(qa[i].x, qa[i].y), klo, s0);
                s1 = ffma2(make_float2(qa[i].z, qa[i].w), khi, s1);
                u0 = ffma2(make_float2(qb[i].x, qb[i].y), klo, u0);
                u1 = ffma2(make_float2(qb[i].z, qb[i].w), khi, u1);
            }
            float sea = s0.x + s0.y + s1.x + s1.y + bj;
            float seb = u0.x + u0.y + u1.x + u1.y + bj;

            const float2* vr = (const float2*)&vs[j * 8];
            if (sea > ma) {
                float corr = ex2f(ma - sea);
                ma = sea;
                la = la * corr + 1.0f;
                float2 cc = make_float2(corr, corr);
#pragma unroll
                for (int i = 0; i < 16; i++) oa[i] = ffma2(cc, oa[i], vr[i]);
            } else {
                float p = ex2f(sea - ma);
                la += p;
                float2 pp = make_float2(p, p);
#pragma unroll
                for (int i = 0; i < 16; i++) oa[i] = ffma2(pp, vr[i], oa[i]);
            }
            if (seb > mb) {
                float corr = ex2f(mb - seb);
                mb = seb;
                lb = lb * corr + 1.0f;
                float2 cc = make_float2(corr, corr);
#pragma unroll
                for (int i = 0; i < 16; i++) ob[i] = ffma2(cc, ob[i], vr[i]);
            } else {
                float p = ex2f(seb - mb);
                lb += p;
                float2 pp = make_float2(p, p);
#pragma unroll
                for (int i = 0; i < 16; i++) ob[i] = ffma2(pp, vr[i], ob[i]);
            }
        }
        __syncthreads();
    }
    float inva = 1.0f / la, invb = 1.0f / lb;
    float* AOa = g_ao + (size_t)bh * BH_STRIDE + (size_t)q0 * DH;
    float* AOb = g_ao + (size_t)bh * BH_STRIDE + (size_t)(q0 + 128) * DH;
#pragma unroll
    for (int i = 0; i < 8; i++) {
        float4 v;
        v.x = oa[2 * i].x * inva;     v.y = oa[2 * i].y * inva;
        v.z = oa[2 * i + 1].x * inva; v.w = oa[2 * i + 1].y * inva;
        ((float4*)AOa)[i] = v;
        float4 w;
        w.x = ob[2 * i].x * invb;     w.y = ob[2 * i].y * invb;
        w.z = ob[2 * i + 1].x * invb; w.w = ob[2 * i + 1].y * invb;
        ((float4*)AOb)[i] = w;
    }
}

// ---------------------------------------------------------------------------
// 9) Output projection GEMM: out[b][c][n] = Wproj @ ao + bproj (f32x2 inner)
// ---------------------------------------------------------------------------
__global__ __launch_bounds__(256) void k_proj(const float* __restrict__ bproj,
                                              float* __restrict__ out) {
    __shared__ float as[16][68];
    __shared__ float bs[16][68];
    int nt = blockIdx.x, mt = blockIdx.y, b = blockIdx.z;
    int t = threadIdx.x;
    int tx4 = (t & 15) * 4, ty4 = (t >> 4) * 4;
    int n0 = nt * 64, m0 = mt * 64;
    int lr = t >> 4, lc4 = (t & 15) * 4;

    const float* Wt = g_Wt + 3 * 65536;
    const float* AOb = g_ao + (size_t)b * B_STRIDE;

    float2 acc2[4][2];
#pragma unroll
    for (int i = 0; i < 4; i++) { acc2[i][0] = make_float2(0.f, 0.f); acc2[i][1] = make_float2(0.f, 0.f); }
    for (int kk = 0; kk < 256; kk += 16) {
        if (kk) __syncthreads();
        *(float4*)&as[lr][lc4] = *(const float4*)&Wt[(kk + lr) * 256 + m0 + lc4];
#pragma unroll
        for (int i = 0; i < 4; i++) {
            int lin = t + i * 256;
            int orow = lin & 15, nc = lin >> 4;
            int o = kk + orow;
            bs[orow][nc] = AOb[((size_t)(o >> 5) * NPIX + n0 + nc) * DH + (o & 31)];
        }
        __syncthreads();
#pragma unroll
        for (int k = 0; k < 16; k++) {
            float4 a4 = *(const float4*)&as[k][ty4];
            float4 b4 = *(const float4*)&bs[k][tx4];
            float2 b01 = make_float2(b4.x, b4.y), b23 = make_float2(b4.z, b4.w);
            float av[4] = { a4.x, a4.y, a4.z, a4.w };
#pragma unroll
            for (int i = 0; i < 4; i++) {
                float2 ai = make_float2(av[i], av[i]);
                acc2[i][0] = ffma2(ai, b01, acc2[i][0]);
                acc2[i][1] = ffma2(ai, b23, acc2[i][1]);
            }
        }
    }
#pragma unroll
    for (int i = 0; i < 4; i++) {
        int mrow = m0 + ty4 + i;
        float bp = bproj[mrow];
        float4 v = make_float4(acc2[i][0].x + bp, acc2[i][0].y + bp,
                               acc2[i][1].x + bp, acc2[i][1].y + bp);
        *(float4*)&out[((size_t)b * CCH + mrow) * NPIX + n0 + tx4] = v;
    }
}

// ---------------------------------------------------------------------------
// launch
// ---------------------------------------------------------------------------
extern "C" void kernel_launch(void* const* d_in, const int* in_sizes, int n_in,
                              void* d_out, int out_size) {
    const float* x     = (const float*)d_in[0];
    const float* rgb   = (const float*)d_in[1];
    const float* wq    = (const float*)d_in[2];
    const float* bq    = (const float*)d_in[3];
    const float* wk    = (const float*)d_in[4];
    const float* bk    = (const float*)d_in[5];
    const float* wv    = (const float*)d_in[6];
    const float* bv    = (const float*)d_in[7];
    const float* wproj = (const float*)d_in[8];
    const float* bproj = (const float*)d_in[9];
    const float* c1w   = (const float*)d_in[10];
    const float* c1b   = (const float*)d_in[11];
    const float* c2w   = (const float*)d_in[12];
    const float* c2b   = (const float*)d_in[13];
    const float* alpha = (const float*)d_in[26];

    FilmArgs fa;
    fa.w[0] = (const float*)d_in[14]; fa.b[0] = (const float*)d_in[15];
    fa.w[1] = (const float*)d_in[16]; fa.b[1] = (const float*)d_in[17];
    fa.w[2] = (const float*)d_in[18]; fa.b[2] = (const float*)d_in[19];
    fa.w[3] = (const float*)d_in[20]; fa.b[3] = (const float*)d_in[21];
    fa.w[4] = (const float*)d_in[22]; fa.b[4] = (const float*)d_in[23];
    fa.w[5] = (const float*)d_in[24]; fa.b[5] = (const float*)d_in[25];

    k_transpose<<<dim3(256, 4), 256>>>(wq, wk, wv, wproj);
    k_lumabias<<<BSZ, 256>>>(rgb, alpha);
    k_conv1<<<dim3(HID, BSZ), 256>>>(c1w, c1b);
    k_conv2mean<<<dim3(HID / 4, BSZ), 256>>>(c2w, c2b);
    k_film<<<dim3(6, BSZ), 256>>>(fa);
    k_qkv<<<dim3(36, 4, 12), 256>>>(x, bq, bk, bv);
    k_attn<<<dim3(9, 32), 128>>>();
    k_proj<<<dim3(36, 4, 4), 256>>>(bproj, (float*)d_out);
}

// round 8
// speedup vs baseline: 1.9450x; 1.8984x over previous
#include <cuda_runtime.h>
#include <cstdint>

// ---------------------------------------------------------------------------
// Problem constants
// ---------------------------------------------------------------------------
#define BSZ    4
#define CCH    256
#define HH     48
#define WW     48
#define NPIX   2304          // 48*48
#define HEADS  8
#define DH     32
#define INNER  256
#define HID    128
#define LOG2E  1.4426950408889634f
#define QSC    (0.17677669529663687f * 1.4426950408889634f)

// ---------------------------------------------------------------------------
// Scratch
// ---------------------------------------------------------------------------
__device__ float g_Wt[4 * 256 * 256];
__device__ float g_luma[BSZ * NPIX];
__device__ float g_biasE[BSZ * NPIX];
__device__ float g_h1[BSZ * HID * NPIX];
__device__ float g_hmp[3 * BSZ * HID];         // 3 band partials
__device__ float g_film[BSZ * 6 * 256];
__device__ float g_qkv[3 * BSZ * HEADS * NPIX * DH];   // [pr][b][h][n][d]
__device__ float g_ao[BSZ * HEADS * NPIX * DH];

#define PR_STRIDE (BSZ * HEADS * NPIX * DH)
#define BH_STRIDE (NPIX * DH)
#define B_STRIDE  (HEADS * NPIX * DH)

// ---------------------------------------------------------------------------
// Helpers
// ---------------------------------------------------------------------------
static __device__ __forceinline__ float2 ffma2(float2 a, float2 b, float2 c) {
    float2 d;
    asm("fma.rn.f32x2 %0, %1, %2, %3;"
        : "=l"(reinterpret_cast<unsigned long long&>(d))
        : "l"(reinterpret_cast<unsigned long long&>(a)),
          "l"(reinterpret_cast<unsigned long long&>(b)),
          "l"(reinterpret_cast<unsigned long long&>(c)));
    return d;
}
static __device__ __forceinline__ float ex2f(float x) {
    float r;
    asm("ex2.approx.f32 %0, %1;" : "=f"(r) : "f"(x));
    return r;
}
static __device__ __forceinline__ uint32_t tf32c(float f) {
    uint32_t u;
    asm("cvt.rna.tf32.f32 %0, %1;" : "=r"(u) : "f"(f));
    return u;
}
static __device__ __forceinline__ void mma_tf32(float* d, const uint32_t* a,
                                                uint32_t b0, uint32_t b1) {
    asm("mma.sync.aligned.m16n8k8.row.col.f32.tf32.tf32.f32 "
        "{%0,%1,%2,%3}, {%4,%5,%6,%7}, {%8,%9}, {%0,%1,%2,%3};"
        : "+f"(d[0]), "+f"(d[1]), "+f"(d[2]), "+f"(d[3])
        : "r"(a[0]), "r"(a[1]), "r"(a[2]), "r"(a[3]), "r"(b0), "r"(b1));
}

// ---------------------------------------------------------------------------
// 1) Weight transposes
// ---------------------------------------------------------------------------
__global__ void k_transpose(const float* __restrict__ wq, const float* __restrict__ wk,
                            const float* __restrict__ wv, const float* __restrict__ wp) {
    int slot = blockIdx.y, r = blockIdx.x, t = threadIdx.x;
    const float* src = (slot == 0) ? wq : (slot == 1) ? wk : (slot == 2) ? wv : wp;
    g_Wt[slot * 65536 + r * 256 + t] = src[t * 256 + r];
}

// ---------------------------------------------------------------------------
// 2) Luma + key bias, fused
// ---------------------------------------------------------------------------
__global__ void k_lumabias(const float* __restrict__ rgb, const float* __restrict__ alpha_p) {
    __shared__ float sy[NPIX];
    __shared__ float pli[2500];
    __shared__ float red[256];
    int b = blockIdx.x, t = threadIdx.x;
    const float* rp = rgb + (size_t)b * 3 * NPIX;
    float lmn = 1e30f, lmx = -1e30f;
#pragma unroll
    for (int k = 0; k < 9; k++) {
        int p = t + k * 256;
        float y = 0.299f * rp[p] + 0.587f * rp[NPIX + p] + 0.114f * rp[2 * NPIX + p];
        sy[p] = y;
        lmn = fminf(lmn, y); lmx = fmaxf(lmx, y);
    }
    red[t] = lmn; __syncthreads();
    for (int s = 128; s > 0; s >>= 1) { if (t < s) red[t] = fminf(red[t], red[t + s]); __syncthreads(); }
    float mn = red[0]; __syncthreads();
    red[t] = lmx; __syncthreads();
    for (int s = 128; s > 0; s >>= 1) { if (t < s) red[t] = fmaxf(red[t], red[t + s]); __syncthreads(); }
    float mx = red[0]; __syncthreads();
    float inv = 1.0f / (mx - mn + 1e-6f);

    for (int i = t; i < 2500; i += 256) pli[i] = 0.f;
    __syncthreads();
#pragma unroll
    for (int k = 0; k < 9; k++) {
        int p = t + k * 256;
        float ln = (sy[p] - mn) * inv;
        g_luma[b * NPIX + p] = ln;
        pli[(p / 48 + 1) * 50 + (p % 48) + 1] = 1.0f - ln;
    }
    __syncthreads();
    float lsum = 0.f;
#pragma unroll
    for (int k = 0; k < 9; k++) {
        int p = t + k * 256;
        int bi = (p / 48 + 1) * 50 + (p % 48) + 1;
        float s = pli[bi - 51] + pli[bi - 50] + pli[bi - 49]
                + pli[bi - 1]  + pli[bi]      + pli[bi + 1]
                + pli[bi + 49] + pli[bi + 50] + pli[bi + 51];
        s *= (1.0f / 9.0f);
        sy[p] = s; lsum += s;
    }
    red[t] = lsum; __syncthreads();
    for (int s = 128; s > 0; s >>= 1) { if (t < s) red[t] += red[t + s]; __syncthreads(); }
    float mean = red[0] * (1.0f / (float)NPIX);
    float a = *alpha_p;
#pragma unroll
    for (int k = 0; k < 9; k++) {
        int p = t + k * 256;
        g_biasE[b * NPIX + p] = a * (sy[p] - mean) * LOG2E;
    }
}

// ---------------------------------------------------------------------------
// 3) Conv1: luma[1ch] -> h1[128ch], 3x3 SAME, ReLU
// ---------------------------------------------------------------------------
__global__ void k_conv1(const float* __restrict__ w1, const float* __restrict__ b1) {
    __shared__ float pl[2500];
    int oc = blockIdx.x, b = blockIdx.y, t = threadIdx.x;
    for (int i = t; i < 2500; i += 256) pl[i] = 0.f;
    __syncthreads();
    const float* L = g_luma + b * NPIX;
#pragma unroll
    for (int k = 0; k < 9; k++) {
        int p = t + k * 256;
        pl[(p / 48 + 1) * 50 + (p % 48) + 1] = L[p];
    }
    __syncthreads();
    float w[9];
#pragma unroll
    for (int i = 0; i < 9; i++) w[i] = w1[oc * 9 + i];
    float bb = b1[oc];
    float* dst = g_h1 + ((size_t)(b * HID + oc)) * NPIX;
#pragma unroll
    for (int k = 0; k < 9; k++) {
        int p = t + k * 256;
        int bi = (p / 48 + 1) * 50 + (p % 48) + 1;
        float s = bb
            + pl[bi - 51] * w[0] + pl[bi - 50] * w[1] + pl[bi - 49] * w[2]
            + pl[bi - 1]  * w[3] + pl[bi]      * w[4] + pl[bi + 1]  * w[5]
            + pl[bi + 49] * w[6] + pl[bi + 50] * w[7] + pl[bi + 51] * w[8];
        dst[p] = fmaxf(s, 0.f);
    }
}

// ---------------------------------------------------------------------------
// 4) Conv2 + ReLU + spatial mean (partial per band).
//    grid (32 ocg, 4 b, 3 band), block (16,16). Thread: 4 contiguous px,
//    register rows + shfl halo, NO smem in the ic loop, no syncthreads.
// ---------------------------------------------------------------------------
__global__ __launch_bounds__(256) void k_conv2mean(const float* __restrict__ w2,
                                                   const float* __restrict__ b2) {
    __shared__ float wsm[128 * 36];   // [ic][tap][oc4]
    int ocg = blockIdx.x, b = blockIdx.y, band = blockIdx.z;
    int tx = threadIdx.x, ty = threadIdx.y;
    int t = ty * 16 + tx;

    for (int i = t; i < 128 * 36; i += 256) {
        int ic = i / 36, r = i % 36;
        int tap = r >> 2, oc = r & 3;
        wsm[i] = w2[(((ocg * 4 + oc) * 128) + ic) * 9 + tap];
    }
    __syncthreads();

    int row = band * 16 + ty;
    int col0 = tx * 4;
    bool active = (tx < 12);

    float2 acc2[4][2];
#pragma unroll
    for (int j = 0; j < 4; j++) { acc2[j][0] = make_float2(0.f, 0.f); acc2[j][1] = make_float2(0.f, 0.f); }

    for (int ic = 0; ic < 128; ++ic) {
        const float* src = g_h1 + ((size_t)(b * HID + ic)) * NPIX;
        float4 h[3];
#pragma unroll
        for (int r = 0; r < 3; r++) {
            int rr = row - 1 + r;
            float4 hv = make_float4(0.f, 0.f, 0.f, 0.f);
            if (active && rr >= 0 && rr < 48) hv = *(const float4*)&src[rr * 48 + col0];
            h[r] = hv;
        }
        float hl[3], hr[3];
#pragma unroll
        for (int r = 0; r < 3; r++) {
            float l = __shfl_up_sync(0xffffffffu, h[r].w, 1);
            float rt = __shfl_down_sync(0xffffffffu, h[r].x, 1);
            hl[r] = (tx == 0) ? 0.f : l;
            hr[r] = (tx >= 11) ? 0.f : rt;
        }
        const float4* wv = (const float4*)&wsm[ic * 36];
#pragma unroll
        for (int r = 0; r < 3; r++) {
            float v[6] = { hl[r], h[r].x, h[r].y, h[r].z, h[r].w, hr[r] };
#pragma unroll
            for (int tc = 0; tc < 3; tc++) {
                float4 w4 = wv[r * 3 + tc];
                float2 wlo = make_float2(w4.x, w4.y), whi = make_float2(w4.z, w4.w);
#pragma unroll
                for (int j = 0; j < 4; j++) {
                    float vv = v[j + tc];
                    float2 tt = make_float2(vv, vv);
                    acc2[j][0] = ffma2(tt, wlo, acc2[j][0]);
                    acc2[j][1] = ffma2(tt, whi, acc2[j][1]);
                }
            }
        }
    }
    // bias + ReLU + per-thread partial sum
    float bb[4] = { b2[ocg * 4 + 0], b2[ocg * 4 + 1], b2[ocg * 4 + 2], b2[ocg * 4 + 3] };
    float prt[4] = { 0.f, 0.f, 0.f, 0.f };
    if (active) {
#pragma unroll
        for (int j = 0; j < 4; j++) {
            prt[0] += fmaxf(acc2[j][0].x + bb[0], 0.f);
            prt[1] += fmaxf(acc2[j][0].y + bb[1], 0.f);
            prt[2] += fmaxf(acc2[j][1].x + bb[2], 0.f);
            prt[3] += fmaxf(acc2[j][1].y + bb[3], 0.f);
        }
    }
    __syncthreads();   // wsm reuse as reduction buffer
    for (int oc = 0; oc < 4; oc++) {
        wsm[t] = prt[oc];
        __syncthreads();
        for (int s = 128; s > 0; s >>= 1) { if (t < s) wsm[t] += wsm[t + s]; __syncthreads(); }
        if (t == 0) g_hmp[(band * BSZ + b) * HID + ocg * 4 + oc] = wsm[0] * (1.0f / (float)NPIX);
        __syncthreads();
    }
}

// ---------------------------------------------------------------------------
// 5) FiLM parameter GEMVs (sums 3 conv2 band partials)
// ---------------------------------------------------------------------------
struct FilmArgs { const float* w[6]; const float* b[6]; };

__global__ void k_film(FilmArgs fa) {
    int s = blockIdx.x, b = blockIdx.y, o = threadIdx.x;
    __shared__ float sh[HID];
    if (threadIdx.x < HID) {
        int h = threadIdx.x;
        sh[h] = g_hmp[(0 * BSZ + b) * HID + h] + g_hmp[(1 * BSZ + b) * HID + h]
              + g_hmp[(2 * BSZ + b) * HID + h];
    }
    __syncthreads();
    const float* W = fa.w[s] + o * HID;
    float acc = fa.b[s][o];
#pragma unroll 8
    for (int h = 0; h < HID; h++) acc += sh[h] * W[h];
    g_film[(b * 6 + s) * 256 + o] = acc;
}

// ---------------------------------------------------------------------------
// 6) QKV GEMM (+ bias + FiLM), output [pr][b][h][n][d]
// ---------------------------------------------------------------------------
__global__ __launch_bounds__(256) void k_qkv(const float* __restrict__ x,
                                             const float* __restrict__ bq,
                                             const float* __restrict__ bk,
                                             const float* __restrict__ bv) {
    __shared__ float as[16][68];
    __shared__ float bs[16][68];
    int nt = blockIdx.x, mt = blockIdx.y, z = blockIdx.z;
    int pr = z >> 2, b = z & 3;
    int t = threadIdx.x;
    int tx4 = (t & 15) * 4, ty4 = (t >> 4) * 4;
    int n0 = nt * 64, o0 = mt * 64;
    int lr = t >> 4, lc4 = (t & 15) * 4;

    const float* Wt = g_Wt + pr * 65536;
    const float* xb = x + (size_t)b * CCH * NPIX;

    float2 acc2[4][2];
#pragma unroll
    for (int i = 0; i < 4; i++) { acc2[i][0] = make_float2(0.f, 0.f); acc2[i][1] = make_float2(0.f, 0.f); }
    for (int kk = 0; kk < 256; kk += 16) {
        if (kk) __syncthreads();
        *(float4*)&as[lr][lc4] = *(const float4*)&Wt[(kk + lr) * 256 + o0 + lc4];
        *(float4*)&bs[lr][lc4] = *(const float4*)&xb[(size_t)(kk + lr) * NPIX + n0 + lc4];
        __syncthreads();
#pragma unroll
        for (int k = 0; k < 16; k++) {
            float4 a4 = *(const float4*)&as[k][ty4];
            float4 b4 = *(const float4*)&bs[k][tx4];
            float2 b01 = make_float2(b4.x, b4.y), b23 = make_float2(b4.z, b4.w);
            float av[4] = { a4.x, a4.y, a4.z, a4.w };
#pragma unroll
            for (int i = 0; i < 4; i++) {
                float2 ai = make_float2(av[i], av[i]);
                acc2[i][0] = ffma2(ai, b01, acc2[i][0]);
                acc2[i][1] = ffma2(ai, b23, acc2[i][1]);
            }
        }
    }
    float acc[4][4];
#pragma unroll
    for (int i = 0; i < 4; i++) {
        acc[i][0] = acc2[i][0].x; acc[i][1] = acc2[i][0].y;
        acc[i][2] = acc2[i][1].x; acc[i][3] = acc2[i][1].y;
    }
    const float* fg  = g_film + (b * 6 + 2 * pr) * 256;
    const float* fb2 = g_film + (b * 6 + 2 * pr + 1) * 256;
    const float* bias = (pr == 0) ? bq : (pr == 1) ? bk : bv;
    int ob = o0 + ty4;
    int h = ob >> 5, d0 = ob & 31;
    float gg[4], be[4], bi[4];
#pragma unroll
    for (int i = 0; i < 4; i++) { gg[i] = fg[ob + i]; be[i] = fb2[ob + i]; bi[i] = bias[ob + i]; }
    float* outb = g_qkv + (size_t)pr * PR_STRIDE + (size_t)b * B_STRIDE;
#pragma unroll
    for (int j = 0; j < 4; j++) {
        int n = n0 + tx4 + j;
        float4 v;
        v.x = gg[0] * (acc[0][j] + bi[0]) + be[0];
        v.y = gg[1] * (acc[1][j] + bi[1]) + be[1];
        v.z = gg[2] * (acc[2][j] + bi[2]) + be[2];
        v.w = gg[3] * (acc[3][j] + bi[3]) + be[3];
        *(float4*)&outb[((size_t)h * NPIX + n) * DH + d0] = v;
    }
}

// ---------------------------------------------------------------------------
// 7) Flash attention with tf32 mma.sync tensor cores.
//    Block: 256 thr = 8 warps, 128 q rows (16/warp). grid (18, 32 bh).
//    Dynamic smem: K tile (stride 36), V tile (stride 40), P stage (stride 68).
// ---------------------------------------------------------------------------
#define KS_STRIDE 36
#define VS_STRIDE 40
#define PS_STRIDE 68
#define ATTN_SMEM ((64 * KS_STRIDE + 64 * VS_STRIDE + 8 * 16 * PS_STRIDE + 64) * 4)

__global__ __launch_bounds__(256) void k_attn() {
    extern __shared__ float smp[];
    float* ksm = smp;                        // 64 x 36
    float* vsm = ksm + 64 * KS_STRIDE;       // 64 x 40
    float* psm = vsm + 64 * VS_STRIDE;       // 8 warps x 16 x 68
    float* bsm = psm + 8 * 16 * PS_STRIDE;   // 64

    int t = threadIdx.x;
    int warp = t >> 5, lane = t & 31;
    int gid = lane >> 2, tig = lane & 3;
    int bh = blockIdx.y;
    int b = bh >> 3;

    const float* Qb = g_qkv + (size_t)bh * BH_STRIDE;
    const float* Kb = g_qkv + (size_t)PR_STRIDE + (size_t)bh * BH_STRIDE;
    const float* Vb = g_qkv + (size_t)2 * PR_STRIDE + (size_t)bh * BH_STRIDE;
    const float* bE = g_biasE + b * NPIX;

    int qr = blockIdx.x * 128 + warp * 16 + gid;

    // Q fragments (A, tf32), QSC folded in
    uint32_t aq[4][4];
#pragma unroll
    for (int ks = 0; ks < 4; ks++) {
        aq[ks][0] = tf32c(Qb[(size_t)qr * 32 + ks * 8 + tig] * QSC);
        aq[ks][1] = tf32c(Qb[(size_t)(qr + 8) * 32 + ks * 8 + tig] * QSC);
        aq[ks][2] = tf32c(Qb[(size_t)qr * 32 + ks * 8 + tig + 4] * QSC);
        aq[ks][3] = tf32c(Qb[(size_t)(qr + 8) * 32 + ks * 8 + tig + 4] * QSC);
    }

    float o[4][4];
#pragma unroll
    for (int i = 0; i < 4; i++)
#pragma unroll
        for (int j = 0; j < 4; j++) o[i][j] = 0.f;
    float m0 = -1e30f, m1 = -1e30f, l0 = 0.f, l1 = 0.f;

    float* pw = psm + warp * 16 * PS_STRIDE;

    for (int nk = 0; nk < 36; ++nk) {
        // load + convert K/V tile (64 x 32 each)
        const float4* Kg = (const float4*)Kb + nk * 512;
        const float4* Vg = (const float4*)Vb + nk * 512;
#pragma unroll
        for (int i = t; i < 512; i += 256) {
            int key = i >> 3, dq = i & 7;
            float4 kv = Kg[i];
            float4 vv = Vg[i];
            float4 kc, vc;
            kc.x = __uint_as_float(tf32c(kv.x)); kc.y = __uint_as_float(tf32c(kv.y));
            kc.z = __uint_as_float(tf32c(kv.z)); kc.w = __uint_as_float(tf32c(kv.w));
            vc.x = __uint_as_float(tf32c(vv.x)); vc.y = __uint_as_float(tf32c(vv.y));
            vc.z = __uint_as_float(tf32c(vv.z)); vc.w = __uint_as_float(tf32c(vv.w));
            *(float4*)&ksm[key * KS_STRIDE + dq * 4] = kc;
            *(float4*)&vsm[key * VS_STRIDE + dq * 4] = vc;
        }
        if (t < 64) bsm[t] = bE[nk * 64 + t];
        __syncthreads();

        // S = Q K^T  (16 x 64 per warp)
        float s[8][4];
#pragma unroll
        for (int nt = 0; nt < 8; nt++)
#pragma unroll
            for (int c = 0; c < 4; c++) s[nt][c] = 0.f;
#pragma unroll
        for (int ks = 0; ks < 4; ks++) {
#pragma unroll
            for (int nt = 0; nt < 8; nt++) {
                int kb = (nt * 8 + gid) * KS_STRIDE + ks * 8 + tig;
                uint32_t b0 = __float_as_uint(ksm[kb]);
                uint32_t b1 = __float_as_uint(ksm[kb + 4]);
                mma_tf32(s[nt], aq[ks], b0, b1);
            }
        }
        // bias + row max
        float mx0 = -1e30f, mx1 = -1e30f;
#pragma unroll
        for (int nt = 0; nt < 8; nt++) {
            float b0v = bsm[nt * 8 + 2 * tig];
            float b1v = bsm[nt * 8 + 2 * tig + 1];
            s[nt][0] += b0v; s[nt][1] += b1v;
            s[nt][2] += b0v; s[nt][3] += b1v;
            mx0 = fmaxf(mx0, fmaxf(s[nt][0], s[nt][1]));
            mx1 = fmaxf(mx1, fmaxf(s[nt][2], s[nt][3]));
        }
        mx0 = fmaxf(mx0, __shfl_xor_sync(0xffffffffu, mx0, 1));
        mx0 = fmaxf(mx0, __shfl_xor_sync(0xffffffffu, mx0, 2));
        mx1 = fmaxf(mx1, __shfl_xor_sync(0xffffffffu, mx1, 1));
        mx1 = fmaxf(mx1, __shfl_xor_sync(0xffffffffu, mx1, 2));

        float mn0 = fmaxf(m0, mx0), mn1 = fmaxf(m1, mx1);
        float c0 = ex2f(m0 - mn0), c1 = ex2f(m1 - mn1);
        m0 = mn0; m1 = mn1;

        float rs0 = 0.f, rs1 = 0.f;
#pragma unroll
        for (int nt = 0; nt < 8; nt++) {
            float p00 = ex2f(s[nt][0] - mn0);
            float p01 = ex2f(s[nt][1] - mn0);
            float p10 = ex2f(s[nt][2] - mn1);
            float p11 = ex2f(s[nt][3] - mn1);
            rs0 += p00 + p01; rs1 += p10 + p11;
            float2 lo, hi;
            lo.x = __uint_as_float(tf32c(p00)); lo.y = __uint_as_float(tf32c(p01));
            hi.x = __uint_as_float(tf32c(p10)); hi.y = __uint_as_float(tf32c(p11));
            *(float2*)&pw[gid * PS_STRIDE + nt * 8 + 2 * tig] = lo;
            *(float2*)&pw[(gid + 8) * PS_STRIDE + nt * 8 + 2 * tig] = hi;
        }
        rs0 += __shfl_xor_sync(0xffffffffu, rs0, 1);
        rs0 += __shfl_xor_sync(0xffffffffu, rs0, 2);
        rs1 += __shfl_xor_sync(0xffffffffu, rs1, 1);
        rs1 += __shfl_xor_sync(0xffffffffu, rs1, 2);
        l0 = l0 * c0 + rs0;
        l1 = l1 * c1 + rs1;
#pragma unroll
        for (int nt = 0; nt < 4; nt++) {
            o[nt][0] *= c0; o[nt][1] *= c0;
            o[nt][2] *= c1; o[nt][3] *= c1;
        }
        __syncwarp();

        // O += P V  (16 x 32 per warp)
#pragma unroll
        for (int ks = 0; ks < 8; ks++) {
            uint32_t a[4];
            a[0] = __float_as_uint(pw[gid * PS_STRIDE + ks * 8 + tig]);
            a[1] = __float_as_uint(pw[(gid + 8) * PS_STRIDE + ks * 8 + tig]);
            a[2] = __float_as_uint(pw[gid * PS_STRIDE + ks * 8 + tig + 4]);
            a[3] = __float_as_uint(pw[(gid + 8) * PS_STRIDE + ks * 8 + tig + 4]);
#pragma unroll
            for (int nt = 0; nt < 4; nt++) {
                int vb = (ks * 8 + tig) * VS_STRIDE + nt * 8 + gid;
                uint32_t b0 = __float_as_uint(vsm[vb]);
                uint32_t b1 = __float_as_uint(vsm[vb + 4 * VS_STRIDE]);
                mma_tf32(o[nt], a, b0, b1);
            }
        }
        __syncthreads();
    }

    float i0 = 1.0f / l0, i1 = 1.0f / l1;
    float* AO = g_ao + (size_t)bh * BH_STRIDE;
#pragma unroll
    for (int nt = 0; nt < 4; nt++) {
        float2 lo = make_float2(o[nt][0] * i0, o[nt][1] * i0);
        float2 hi = make_float2(o[nt][2] * i1, o[nt][3] * i1);
        *(float2*)&AO[(size_t)qr * 32 + nt * 8 + 2 * tig] = lo;
        *(float2*)&AO[(size_t)(qr + 8) * 32 + nt * 8 + 2 * tig] = hi;
    }
}

// ---------------------------------------------------------------------------
// 8) Output projection GEMM
// ---------------------------------------------------------------------------
__global__ __launch_bounds__(256) void k_proj(const float* __restrict__ bproj,
                                              float* __restrict__ out) {
    __shared__ float as[16][68];
    __shared__ float bs[16][68];
    int nt = blockIdx.x, mt = blockIdx.y, b = blockIdx.z;
    int t = threadIdx.x;
    int tx4 = (t & 15) * 4, ty4 = (t >> 4) * 4;
    int n0 = nt * 64, m0 = mt * 64;
    int lr = t >> 4, lc4 = (t & 15) * 4;

    const float* Wt = g_Wt + 3 * 65536;
    const float* AOb = g_ao + (size_t)b * B_STRIDE;

    float2 acc2[4][2];
#pragma unroll
    for (int i = 0; i < 4; i++) { acc2[i][0] = make_float2(0.f, 0.f); acc2[i][1] = make_float2(0.f, 0.f); }
    for (int kk = 0; kk < 256; kk += 16) {
        if (kk) __syncthreads();
        *(float4*)&as[lr][lc4] = *(const float4*)&Wt[(kk + lr) * 256 + m0 + lc4];
#pragma unroll
        for (int i = 0; i < 4; i++) {
            int lin = t + i * 256;
            int orow = lin & 15, nc = lin >> 4;
            int o = kk + orow;
            bs[orow][nc] = AOb[((size_t)(o >> 5) * NPIX + n0 + nc) * DH + (o & 31)];
        }
        __syncthreads();
#pragma unroll
        for (int k = 0; k < 16; k++) {
            float4 a4 = *(const float4*)&as[k][ty4];
            float4 b4 = *(const float4*)&bs[k][tx4];
            float2 b01 = make_float2(b4.x, b4.y), b23 = make_float2(b4.z, b4.w);
            float av[4] = { a4.x, a4.y, a4.z, a4.w };
#pragma unroll
            for (int i = 0; i < 4; i++) {
                float2 ai = make_float2(av[i], av[i]);
                acc2[i][0] = ffma2(ai, b01, acc2[i][0]);
                acc2[i][1] = ffma2(ai, b23, acc2[i][1]);
            }
        }
    }
#pragma unroll
    for (int i = 0; i < 4; i++) {
        int mrow = m0 + ty4 + i;
        float bp = bproj[mrow];
        float4 v = make_float4(acc2[i][0].x + bp, acc2[i][0].y + bp,
                               acc2[i][1].x + bp, acc2[i][1].y + bp);
        *(float4*)&out[((size_t)b * CCH + mrow) * NPIX + n0 + tx4] = v;
    }
}

// ---------------------------------------------------------------------------
// launch
// ---------------------------------------------------------------------------
extern "C" void kernel_launch(void* const* d_in, const int* in_sizes, int n_in,
                              void* d_out, int out_size) {
    const float* x     = (const float*)d_in[0];
    const float* rgb   = (const float*)d_in[1];
    const float* wq    = (const float*)d_in[2];
    const float* bq    = (const float*)d_in[3];
    const float* wk    = (const float*)d_in[4];
    const float* bk    = (const float*)d_in[5];
    const float* wv    = (const float*)d_in[6];
    const float* bv    = (const float*)d_in[7];
    const float* wproj = (const float*)d_in[8];
    const float* bproj = (const float*)d_in[9];
    const float* c1w   = (const float*)d_in[10];
    const float* c1b   = (const float*)d_in[11];
    const float* c2w   = (const float*)d_in[12];
    const float* c2b   = (const float*)d_in[13];
    const float* alpha = (const float*)d_in[26];

    FilmArgs fa;
    fa.w[0] = (const float*)d_in[14]; fa.b[0] = (const float*)d_in[15];
    fa.w[1] = (const float*)d_in[16]; fa.b[1] = (const float*)d_in[17];
    fa.w[2] = (const float*)d_in[18]; fa.b[2] = (const float*)d_in[19];
    fa.w[3] = (const float*)d_in[20]; fa.b[3] = (const float*)d_in[21];
    fa.w[4] = (const float*)d_in[22]; fa.b[4] = (const float*)d_in[23];
    fa.w[5] = (const float*)d_in[24]; fa.b[5] = (const float*)d_in[25];

    static bool attr_done = false;
    if (!attr_done) {
        cudaFuncSetAttribute(k_attn, cudaFuncAttributeMaxDynamicSharedMemorySize, ATTN_SMEM);
        attr_done = true;
    }

    k_transpose<<<dim3(256, 4), 256>>>(wq, wk, wv, wproj);
    k_lumabias<<<BSZ, 256>>>(rgb, alpha);
    k_conv1<<<dim3(HID, BSZ), 256>>>(c1w, c1b);
    k_conv2mean<<<dim3(HID / 4, BSZ, 3), dim3(16, 16)>>>(c2w, c2b);
    k_film<<<dim3(6, BSZ), 256>>>(fa);
    k_qkv<<<dim3(36, 4, 12), 256>>>(x, bq, bk, bv);
    k_attn<<<dim3(18, 32), 256, ATTN_SMEM>>>();
    k_proj<<<dim3(36, 4, 4), 256>>>(bproj, (float*)d_out);
}

// round 9
// speedup vs baseline: 2.2899x; 1.1773x over previous
#include <cuda_runtime.h>
#include <cstdint>

// ---------------------------------------------------------------------------
// Problem constants
// ---------------------------------------------------------------------------
#define BSZ    4
#define CCH    256
#define HH     48
#define WW     48
#define NPIX   2304          // 48*48
#define HEADS  8
#define DH     32
#define INNER  256
#define HID    128
#define LOG2E  1.4426950408889634f
#define QSC    (0.17677669529663687f * 1.4426950408889634f)

// ---------------------------------------------------------------------------
// Scratch
// ---------------------------------------------------------------------------
__device__ float g_Wt[4 * 256 * 256];          // tf32 patterns: wq,wk,wv,wproj (row-major as given)
__device__ float g_xt[BSZ * CCH * NPIX];       // tf32 patterns of x
__device__ float g_luma[BSZ * NPIX];
__device__ float g_biasE[BSZ * NPIX];
__device__ float g_h1[BSZ * HID * NPIX];
__device__ float g_hmp[3 * BSZ * HID];
__device__ float g_film[BSZ * 6 * 256];
__device__ float g_qkv[3 * BSZ * HEADS * NPIX * DH];   // [pr][b][h][n][d]; K,V tf32-rounded
__device__ float g_ao[BSZ * HEADS * NPIX * DH];        // tf32-rounded

#define PR_STRIDE (BSZ * HEADS * NPIX * DH)
#define BH_STRIDE (NPIX * DH)
#define B_STRIDE  (HEADS * NPIX * DH)

// ---------------------------------------------------------------------------
// Helpers
// ---------------------------------------------------------------------------
static __device__ __forceinline__ float2 ffma2(float2 a, float2 b, float2 c) {
    float2 d;
    asm("fma.rn.f32x2 %0, %1, %2, %3;"
        : "=l"(reinterpret_cast<unsigned long long&>(d))
        : "l"(reinterpret_cast<unsigned long long&>(a)),
          "l"(reinterpret_cast<unsigned long long&>(b)),
          "l"(reinterpret_cast<unsigned long long&>(c)));
    return d;
}
static __device__ __forceinline__ float ex2f(float x) {
    float r;
    asm("ex2.approx.f32 %0, %1;" : "=f"(r) : "f"(x));
    return r;
}
static __device__ __forceinline__ uint32_t tf32c(float f) {
    uint32_t u;
    asm("cvt.rna.tf32.f32 %0, %1;" : "=r"(u) : "f"(f));
    return u;
}
static __device__ __forceinline__ float tf32f(float f) {
    return __uint_as_float(tf32c(f));
}
static __device__ __forceinline__ void mma_tf32(float* d, const uint32_t* a,
                                                uint32_t b0, uint32_t b1) {
    asm("mma.sync.aligned.m16n8k8.row.col.f32.tf32.tf32.f32 "
        "{%0,%1,%2,%3}, {%4,%5,%6,%7}, {%8,%9}, {%0,%1,%2,%3};"
        : "+f"(d[0]), "+f"(d[1]), "+f"(d[2]), "+f"(d[3])
        : "r"(a[0]), "r"(a[1]), "r"(a[2]), "r"(a[3]), "r"(b0), "r"(b1));
}

// ---------------------------------------------------------------------------
// 0) Prep: convert weights + x to tf32 bit patterns (layouts unchanged).
//    grid 2560, block 256, one float4 per thread.
// ---------------------------------------------------------------------------
__global__ void k_prep(const float* __restrict__ wq, const float* __restrict__ wk,
                       const float* __restrict__ wv, const float* __restrict__ wp,
                       const float* __restrict__ x) {
    int i = blockIdx.x * 256 + threadIdx.x;   // float4 index
    float4 v, c;
    if (i < 65536) {
        int slot = i >> 14, j = i & 16383;
        const float* src = (slot == 0) ? wq : (slot == 1) ? wk : (slot == 2) ? wv : wp;
        v = ((const float4*)src)[j];
        c.x = tf32f(v.x); c.y = tf32f(v.y); c.z = tf32f(v.z); c.w = tf32f(v.w);
        ((float4*)g_Wt)[slot * 16384 + j] = c;
    } else {
        int j = i - 65536;   // < 589824
        v = ((const float4*)x)[j];
        c.x = tf32f(v.x); c.y = tf32f(v.y); c.z = tf32f(v.z); c.w = tf32f(v.w);
        ((float4*)g_xt)[j] = c;
    }
}

// ---------------------------------------------------------------------------
// 1) Luma + key bias, fused
// ---------------------------------------------------------------------------
__global__ void k_lumabias(const float* __restrict__ rgb, const float* __restrict__ alpha_p) {
    __shared__ float sy[NPIX];
    __shared__ float pli[2500];
    __shared__ float red[256];
    int b = blockIdx.x, t = threadIdx.x;
    const float* rp = rgb + (size_t)b * 3 * NPIX;
    float lmn = 1e30f, lmx = -1e30f;
#pragma unroll
    for (int k = 0; k < 9; k++) {
        int p = t + k * 256;
        float y = 0.299f * rp[p] + 0.587f * rp[NPIX + p] + 0.114f * rp[2 * NPIX + p];
        sy[p] = y;
        lmn = fminf(lmn, y); lmx = fmaxf(lmx, y);
    }
    red[t] = lmn; __syncthreads();
    for (int s = 128; s > 0; s >>= 1) { if (t < s) red[t] = fminf(red[t], red[t + s]); __syncthreads(); }
    float mn = red[0]; __syncthreads();
    red[t] = lmx; __syncthreads();
    for (int s = 128; s > 0; s >>= 1) { if (t < s) red[t] = fmaxf(red[t], red[t + s]); __syncthreads(); }
    float mx = red[0]; __syncthreads();
    float inv = 1.0f / (mx - mn + 1e-6f);

    for (int i = t; i < 2500; i += 256) pli[i] = 0.f;
    __syncthreads();
#pragma unroll
    for (int k = 0; k < 9; k++) {
        int p = t + k * 256;
        float ln = (sy[p] - mn) * inv;
        g_luma[b * NPIX + p] = ln;
        pli[(p / 48 + 1) * 50 + (p % 48) + 1] = 1.0f - ln;
    }
    __syncthreads();
    float lsum = 0.f;
#pragma unroll
    for (int k = 0; k < 9; k++) {
        int p = t + k * 256;
        int bi = (p / 48 + 1) * 50 + (p % 48) + 1;
        float s = pli[bi - 51] + pli[bi - 50] + pli[bi - 49]
                + pli[bi - 1]  + pli[bi]      + pli[bi + 1]
                + pli[bi + 49] + pli[bi + 50] + pli[bi + 51];
        s *= (1.0f / 9.0f);
        sy[p] = s; lsum += s;
    }
    red[t] = lsum; __syncthreads();
    for (int s = 128; s > 0; s >>= 1) { if (t < s) red[t] += red[t + s]; __syncthreads(); }
    float mean = red[0] * (1.0f / (float)NPIX);
    float a = *alpha_p;
#pragma unroll
    for (int k = 0; k < 9; k++) {
        int p = t + k * 256;
        g_biasE[b * NPIX + p] = a * (sy[p] - mean) * LOG2E;
    }
}

// ---------------------------------------------------------------------------
// 2) Conv1: luma[1ch] -> h1[128ch], 3x3 SAME, ReLU
// ---------------------------------------------------------------------------
__global__ void k_conv1(const float* __restrict__ w1, const float* __restrict__ b1) {
    __shared__ float pl[2500];
    int oc = blockIdx.x, b = blockIdx.y, t = threadIdx.x;
    for (int i = t; i < 2500; i += 256) pl[i] = 0.f;
    __syncthreads();
    const float* L = g_luma + b * NPIX;
#pragma unroll
    for (int k = 0; k < 9; k++) {
        int p = t + k * 256;
        pl[(p / 48 + 1) * 50 + (p % 48) + 1] = L[p];
    }
    __syncthreads();
    float w[9];
#pragma unroll
    for (int i = 0; i < 9; i++) w[i] = w1[oc * 9 + i];
    float bb = b1[oc];
    float* dst = g_h1 + ((size_t)(b * HID + oc)) * NPIX;
#pragma unroll
    for (int k = 0; k < 9; k++) {
        int p = t + k * 256;
        int bi = (p / 48 + 1) * 50 + (p % 48) + 1;
        float s = bb
            + pl[bi - 51] * w[0] + pl[bi - 50] * w[1] + pl[bi - 49] * w[2]
            + pl[bi - 1]  * w[3] + pl[bi]      * w[4] + pl[bi + 1]  * w[5]
            + pl[bi + 49] * w[6] + pl[bi + 50] * w[7] + pl[bi + 51] * w[8];
        dst[p] = fmaxf(s, 0.f);
    }
}

// ---------------------------------------------------------------------------
// 3) Conv2 + ReLU + spatial mean (band partials), software-pipelined ic loop.
//    grid (32 ocg, 4 b, 3 band), block (16,16).
// ---------------------------------------------------------------------------
__global__ __launch_bounds__(256) void k_conv2mean(const float* __restrict__ w2,
                                                   const float* __restrict__ b2) {
    __shared__ float wsm[128 * 36];   // [ic][tap][oc4]
    int ocg = blockIdx.x, b = blockIdx.y, band = blockIdx.z;
    int tx = threadIdx.x, ty = threadIdx.y;
    int t = ty * 16 + tx;

    for (int i = t; i < 128 * 36; i += 256) {
        int ic = i / 36, r = i % 36;
        int tap = r >> 2, oc = r & 3;
        wsm[i] = w2[(((ocg * 4 + oc) * 128) + ic) * 9 + tap];
    }
    __syncthreads();

    int row = band * 16 + ty;
    int col0 = tx * 4;
    bool active = (tx < 12);
    const float* srcb = g_h1 + ((size_t)(b * HID)) * NPIX;

    float2 acc2[4][2];
#pragma unroll
    for (int j = 0; j < 4; j++) { acc2[j][0] = make_float2(0.f, 0.f); acc2[j][1] = make_float2(0.f, 0.f); }

    // preload ic = 0
    float4 h[3];
#pragma unroll
    for (int r = 0; r < 3; r++) {
        int rr = row - 1 + r;
        float4 hv = make_float4(0.f, 0.f, 0.f, 0.f);
        if (active && rr >= 0 && rr < 48) hv = *(const float4*)&srcb[rr * 48 + col0];
        h[r] = hv;
    }

    for (int ic = 0; ic < 128; ++ic) {
        // prefetch ic+1 rows (overlaps with compute below)
        float4 hn[3];
        if (ic < 127) {
            const float* sn = srcb + (size_t)(ic + 1) * NPIX;
#pragma unroll
            for (int r = 0; r < 3; r++) {
                int rr = row - 1 + r;
                float4 hv = make_float4(0.f, 0.f, 0.f, 0.f);
                if (active && rr >= 0 && rr < 48) hv = *(const float4*)&sn[rr * 48 + col0];
                hn[r] = hv;
            }
        }
        float hl[3], hr[3];
#pragma unroll
        for (int r = 0; r < 3; r++) {
            float l = __shfl_up_sync(0xffffffffu, h[r].w, 1);
            float rt = __shfl_down_sync(0xffffffffu, h[r].x, 1);
            hl[r] = (tx == 0) ? 0.f : l;
            hr[r] = (tx >= 11) ? 0.f : rt;
        }
        const float4* wv = (const float4*)&wsm[ic * 36];
#pragma unroll
        for (int r = 0; r < 3; r++) {
            float v[6] = { hl[r], h[r].x, h[r].y, h[r].z, h[r].w, hr[r] };
#pragma unroll
            for (int tc = 0; tc < 3; tc++) {
                float4 w4 = wv[r * 3 + tc];
                float2 wlo = make_float2(w4.x, w4.y), whi = make_float2(w4.z, w4.w);
#pragma unroll
                for (int j = 0; j < 4; j++) {
                    float vv = v[j + tc];
                    float2 tt = make_float2(vv, vv);
                    acc2[j][0] = ffma2(tt, wlo, acc2[j][0]);
                    acc2[j][1] = ffma2(tt, whi, acc2[j][1]);
                }
            }
        }
#pragma unroll
        for (int r = 0; r < 3; r++) h[r] = hn[r];
    }
    float bb[4] = { b2[ocg * 4 + 0], b2[ocg * 4 + 1], b2[ocg * 4 + 2], b2[ocg * 4 + 3] };
    float prt[4] = { 0.f, 0.f, 0.f, 0.f };
    if (active) {
#pragma unroll
        for (int j = 0; j < 4; j++) {
            prt[0] += fmaxf(acc2[j][0].x + bb[0], 0.f);
            prt[1] += fmaxf(acc2[j][0].y + bb[1], 0.f);
            prt[2] += fmaxf(acc2[j][1].x + bb[2], 0.f);
            prt[3] += fmaxf(acc2[j][1].y + bb[3], 0.f);
        }
    }
    __syncthreads();
    for (int oc = 0; oc < 4; oc++) {
        wsm[t] = prt[oc];
        __syncthreads();
        for (int s = 128; s > 0; s >>= 1) { if (t < s) wsm[t] += wsm[t + s]; __syncthreads(); }
        if (t == 0) g_hmp[(band * BSZ + b) * HID + ocg * 4 + oc] = wsm[0] * (1.0f / (float)NPIX);
        __syncthreads();
    }
}

// ---------------------------------------------------------------------------
// 4) FiLM parameter GEMVs (sums 3 conv2 band partials)
// ---------------------------------------------------------------------------
struct FilmArgs { const float* w[6]; const float* b[6]; };

__global__ void k_film(FilmArgs fa) {
    int s = blockIdx.x, b = blockIdx.y, o = threadIdx.x;
    __shared__ float sh[HID];
    if (threadIdx.x < HID) {
        int h = threadIdx.x;
        sh[h] = g_hmp[(0 * BSZ + b) * HID + h] + g_hmp[(1 * BSZ + b) * HID + h]
              + g_hmp[(2 * BSZ + b) * HID + h];
    }
    __syncthreads();
    const float* W = fa.w[s] + o * HID;
    float acc = fa.b[s][o];
#pragma unroll 8
    for (int h = 0; h < HID; h++) acc += sh[h] * W[h];
    g_film[(b * 6 + s) * 256 + o] = acc;
}

// ---------------------------------------------------------------------------
// 5) QKV GEMM via tf32 mma (+ bias + FiLM). M=128(o) x N=64(px) per block,
//    K=256 in chunks of 32. grid (36, 2, 12), 256 thr (8 warps x m16).
//    K/V outputs tf32-rounded for attention mma; Q stays fp32.
// ---------------------------------------------------------------------------
#define AW_STRIDE 36
#define BX_STRIDE 72

__global__ __launch_bounds__(256) void k_qkv(const float* __restrict__ bq,
                                             const float* __restrict__ bk,
                                             const float* __restrict__ bv) {
    __shared__ float wsm[128 * AW_STRIDE];
    __shared__ float xsm[32 * BX_STRIDE];
    int ntb = blockIdx.x, mt = blockIdx.y, z = blockIdx.z;
    int pr = z >> 2, b = z & 3;
    int t = threadIdx.x, warp = t >> 5, lane = t & 31;
    int gid = lane >> 2, tig = lane & 3;
    int n0 = ntb * 64;

    const float* W = g_Wt + pr * 65536 + mt * 128 * 256;   // tf32 patterns [o][c]
    const float* xb = g_xt + (size_t)b * CCH * NPIX;       // tf32 patterns [c][px]

    float s[8][4];
#pragma unroll
    for (int i = 0; i < 8; i++)
#pragma unroll
        for (int j = 0; j < 4; j++) s[i][j] = 0.f;

    for (int kk = 0; kk < 256; kk += 32) {
        if (kk) __syncthreads();
#pragma unroll
        for (int j = 0; j < 4; j++) {
            int idx = t + j * 256;
            int o = idx >> 3, cg = idx & 7;
            *(float4*)&wsm[o * AW_STRIDE + cg * 4] = *(const float4*)&W[o * 256 + kk + cg * 4];
        }
#pragma unroll
        for (int j = 0; j < 2; j++) {
            int idx = t + j * 256;
            int c = idx >> 4, ng = idx & 15;
            *(float4*)&xsm[c * BX_STRIDE + ng * 4] =
                *(const float4*)&xb[(size_t)(kk + c) * NPIX + n0 + ng * 4];
        }
        __syncthreads();
#pragma unroll
        for (int ks = 0; ks < 4; ks++) {
            uint32_t a[4];
            int ab = (warp * 16 + gid) * AW_STRIDE + ks * 8 + tig;
            a[0] = __float_as_uint(wsm[ab]);
            a[1] = __float_as_uint(wsm[ab + 8 * AW_STRIDE]);
            a[2] = __float_as_uint(wsm[ab + 4]);
            a[3] = __float_as_uint(wsm[ab + 8 * AW_STRIDE + 4]);
#pragma unroll
            for (int nt = 0; nt < 8; nt++) {
                int bbx = (ks * 8 + tig) * BX_STRIDE + nt * 8 + gid;
                mma_tf32(s[nt], a, __float_as_uint(xsm[bbx]),
                         __float_as_uint(xsm[bbx + 4 * BX_STRIDE]));
            }
        }
    }
    // FiLM epilogue
    int o0 = mt * 128 + warp * 16 + gid, o1 = o0 + 8;
    const float* fg  = g_film + (b * 6 + 2 * pr) * 256;
    const float* fb2 = g_film + (b * 6 + 2 * pr + 1) * 256;
    const float* bias = (pr == 0) ? bq : (pr == 1) ? bk : bv;
    float g0 = fg[o0], g1 = fg[o1], e0 = fb2[o0], e1 = fb2[o1];
    float i0 = bias[o0], i1 = bias[o1];
    int h0 = o0 >> 5, d0 = o0 & 31, h1 = o1 >> 5, d1 = o1 & 31;
    float* outb = g_qkv + (size_t)pr * PR_STRIDE + (size_t)b * B_STRIDE;
    bool rnd = (pr != 0);
#pragma unroll
    for (int nt = 0; nt < 8; nt++) {
        int n = n0 + nt * 8 + 2 * tig;
        float v00 = g0 * (s[nt][0] + i0) + e0;
        float v01 = g0 * (s[nt][1] + i0) + e0;
        float v10 = g1 * (s[nt][2] + i1) + e1;
        float v11 = g1 * (s[nt][3] + i1) + e1;
        if (rnd) { v00 = tf32f(v00); v01 = tf32f(v01); v10 = tf32f(v10); v11 = tf32f(v11); }
        outb[((size_t)h0 * NPIX + n) * 32 + d0]     = v00;
        outb[((size_t)h0 * NPIX + n + 1) * 32 + d0] = v01;
        outb[((size_t)h1 * NPIX + n) * 32 + d1]     = v10;
        outb[((size_t)h1 * NPIX + n + 1) * 32 + d1] = v11;
    }
}

// ---------------------------------------------------------------------------
// 6) Flash attention with tf32 mma (K/V pre-rounded by k_qkv).
// ---------------------------------------------------------------------------
#define KS_STRIDE 36
#define VS_STRIDE 40
#define PS_STRIDE 68
#define ATTN_SMEM ((64 * KS_STRIDE + 64 * VS_STRIDE + 8 * 16 * PS_STRIDE + 64) * 4)

__global__ __launch_bounds__(256) void k_attn() {
    extern __shared__ float smp[];
    float* ksm = smp;
    float* vsm = ksm + 64 * KS_STRIDE;
    float* psm = vsm + 64 * VS_STRIDE;
    float* bsm = psm + 8 * 16 * PS_STRIDE;

    int t = threadIdx.x;
    int warp = t >> 5, lane = t & 31;
    int gid = lane >> 2, tig = lane & 3;
    int bh = blockIdx.y;
    int b = bh >> 3;

    const float* Qb = g_qkv + (size_t)bh * BH_STRIDE;
    const float* Kb = g_qkv + (size_t)PR_STRIDE + (size_t)bh * BH_STRIDE;
    const float* Vb = g_qkv + (size_t)2 * PR_STRIDE + (size_t)bh * BH_STRIDE;
    const float* bE = g_biasE + b * NPIX;

    int qr = blockIdx.x * 128 + warp * 16 + gid;

    uint32_t aq[4][4];
#pragma unroll
    for (int ks = 0; ks < 4; ks++) {
        aq[ks][0] = tf32c(Qb[(size_t)qr * 32 + ks * 8 + tig] * QSC);
        aq[ks][1] = tf32c(Qb[(size_t)(qr + 8) * 32 + ks * 8 + tig] * QSC);
        aq[ks][2] = tf32c(Qb[(size_t)qr * 32 + ks * 8 + tig + 4] * QSC);
        aq[ks][3] = tf32c(Qb[(size_t)(qr + 8) * 32 + ks * 8 + tig + 4] * QSC);
    }

    float o[4][4];
#pragma unroll
    for (int i = 0; i < 4; i++)
#pragma unroll
        for (int j = 0; j < 4; j++) o[i][j] = 0.f;
    float m0 = -1e30f, m1 = -1e30f, l0 = 0.f, l1 = 0.f;

    float* pw = psm + warp * 16 * PS_STRIDE;

    for (int nk = 0; nk < 36; ++nk) {
        const float4* Kg = (const float4*)Kb + nk * 512;
        const float4* Vg = (const float4*)Vb + nk * 512;
#pragma unroll
        for (int i = t; i < 512; i += 256) {
            int key = i >> 3, dq = i & 7;
            *(float4*)&ksm[key * KS_STRIDE + dq * 4] = Kg[i];
            *(float4*)&vsm[key * VS_STRIDE + dq * 4] = Vg[i];
        }
        if (t < 64) bsm[t] = bE[nk * 64 + t];
        __syncthreads();

        float s[8][4];
#pragma unroll
        for (int nt = 0; nt < 8; nt++)
#pragma unroll
            for (int c = 0; c < 4; c++) s[nt][c] = 0.f;
#pragma unroll
        for (int ks = 0; ks < 4; ks++) {
#pragma unroll
            for (int nt = 0; nt < 8; nt++) {
                int kb = (nt * 8 + gid) * KS_STRIDE + ks * 8 + tig;
                uint32_t b0 = __float_as_uint(ksm[kb]);
                uint32_t b1 = __float_as_uint(ksm[kb + 4]);
                mma_tf32(s[nt], aq[ks], b0, b1);
            }
        }
        float mx0 = -1e30f, mx1 = -1e30f;
#pragma unroll
        for (int nt = 0; nt < 8; nt++) {
            float b0v = bsm[nt * 8 + 2 * tig];
            float b1v = bsm[nt * 8 + 2 * tig + 1];
            s[nt][0] += b0v; s[nt][1] += b1v;
            s[nt][2] += b0v; s[nt][3] += b1v;
            mx0 = fmaxf(mx0, fmaxf(s[nt][0], s[nt][1]));
            mx1 = fmaxf(mx1, fmaxf(s[nt][2], s[nt][3]));
        }
        mx0 = fmaxf(mx0, __shfl_xor_sync(0xffffffffu, mx0, 1));
        mx0 = fmaxf(mx0, __shfl_xor_sync(0xffffffffu, mx0, 2));
        mx1 = fmaxf(mx1, __shfl_xor_sync(0xffffffffu, mx1, 1));
        mx1 = fmaxf(mx1, __shfl_xor_sync(0xffffffffu, mx1, 2));

        float mn0 = fmaxf(m0, mx0), mn1 = fmaxf(m1, mx1);
        float c0 = ex2f(m0 - mn0), c1 = ex2f(m1 - mn1);
        m0 = mn0; m1 = mn1;

        float rs0 = 0.f, rs1 = 0.f;
#pragma unroll
        for (int nt = 0; nt < 8; nt++) {
            float p00 = ex2f(s[nt][0] - mn0);
            float p01 = ex2f(s[nt][1] - mn0);
            float p10 = ex2f(s[nt][2] - mn1);
            float p11 = ex2f(s[nt][3] - mn1);
            rs0 += p00 + p01; rs1 += p10 + p11;
            float2 lo, hi;
            lo.x = tf32f(p00); lo.y = tf32f(p01);
            hi.x = tf32f(p10); hi.y = tf32f(p11);
            *(float2*)&pw[gid * PS_STRIDE + nt * 8 + 2 * tig] = lo;
            *(float2*)&pw[(gid + 8) * PS_STRIDE + nt * 8 + 2 * tig] = hi;
        }
        rs0 += __shfl_xor_sync(0xffffffffu, rs0, 1);
        rs0 += __shfl_xor_sync(0xffffffffu, rs0, 2);
        rs1 += __shfl_xor_sync(0xffffffffu, rs1, 1);
        rs1 += __shfl_xor_sync(0xffffffffu, rs1, 2);
        l0 = l0 * c0 + rs0;
        l1 = l1 * c1 + rs1;
#pragma unroll
        for (int nt = 0; nt < 4; nt++) {
            o[nt][0] *= c0; o[nt][1] *= c0;
            o[nt][2] *= c1; o[nt][3] *= c1;
        }
        __syncwarp();

#pragma unroll
        for (int ks = 0; ks < 8; ks++) {
            uint32_t a[4];
            a[0] = __float_as_uint(pw[gid * PS_STRIDE + ks * 8 + tig]);
            a[1] = __float_as_uint(pw[(gid + 8) * PS_STRIDE + ks * 8 + tig]);
            a[2] = __float_as_uint(pw[gid * PS_STRIDE + ks * 8 + tig + 4]);
            a[3] = __float_as_uint(pw[(gid + 8) * PS_STRIDE + ks * 8 + tig + 4]);
#pragma unroll
            for (int nt = 0; nt < 4; nt++) {
                int vb = (ks * 8 + tig) * VS_STRIDE + nt * 8 + gid;
                uint32_t b0 = __float_as_uint(vsm[vb]);
                uint32_t b1 = __float_as_uint(vsm[vb + 4 * VS_STRIDE]);
                mma_tf32(o[nt], a, b0, b1);
            }
        }
        __syncthreads();
    }

    float i0 = 1.0f / l0, i1 = 1.0f / l1;
    float* AO = g_ao + (size_t)bh * BH_STRIDE;
#pragma unroll
    for (int nt = 0; nt < 4; nt++) {
        float2 lo = make_float2(tf32f(o[nt][0] * i0), tf32f(o[nt][1] * i0));
        float2 hi = make_float2(tf32f(o[nt][2] * i1), tf32f(o[nt][3] * i1));
        *(float2*)&AO[(size_t)qr * 32 + nt * 8 + 2 * tig] = lo;
        *(float2*)&AO[(size_t)(qr + 8) * 32 + nt * 8 + 2 * tig] = hi;
    }
}

// ---------------------------------------------------------------------------
// 7) Output projection via tf32 mma. M=128(cout) x N=64(px), K=256(inner).
//    grid (36, 2, 4).
// ---------------------------------------------------------------------------
__global__ __launch_bounds__(256) void k_proj(const float* __restrict__ bproj,
                                              float* __restrict__ out) {
    __shared__ float wsm[128 * AW_STRIDE];
    __shared__ float bsm2[32 * BX_STRIDE];
    int ntb = blockIdx.x, mt = blockIdx.y, b = blockIdx.z;
    int t = threadIdx.x, warp = t >> 5, lane = t & 31;
    int gid = lane >> 2, tig = lane & 3;
    int n0 = ntb * 64;

    const float* W = g_Wt + 3 * 65536 + mt * 128 * 256;    // tf32 [cout][o]
    const float* AOb = g_ao + (size_t)b * B_STRIDE;        // tf32 [h][n][d]

    float s[8][4];
#pragma unroll
    for (int i = 0; i < 8; i++)
#pragma unroll
        for (int j = 0; j < 4; j++) s[i][j] = 0.f;

    for (int kk = 0; kk < 256; kk += 32) {
        if (kk) __syncthreads();
#pragma unroll
        for (int j = 0; j < 4; j++) {
            int idx = t + j * 256;
            int o = idx >> 3, cg = idx & 7;
            *(float4*)&wsm[o * AW_STRIDE + cg * 4] = *(const float4*)&W[o * 256 + kk + cg * 4];
        }
#pragma unroll
        for (int j = 0; j < 8; j++) {
            int idx = t + j * 256;
            int c = idx >> 6, ng = idx & 63;
            int o = kk + c;
            bsm2[c * BX_STRIDE + ng] =
                AOb[((size_t)(o >> 5) * NPIX + n0 + ng) * 32 + (o & 31)];
        }
        __syncthreads();
#pragma unroll
        for (int ks = 0; ks < 4; ks++) {
            uint32_t a[4];
            int ab = (warp * 16 + gid) * AW_STRIDE + ks * 8 + tig;
            a[0] = __float_as_uint(wsm[ab]);
            a[1] = __float_as_uint(wsm[ab + 8 * AW_STRIDE]);
            a[2] = __float_as_uint(wsm[ab + 4]);
            a[3] = __float_as_uint(wsm[ab + 8 * AW_STRIDE + 4]);
#pragma unroll
            for (int nt = 0; nt < 8; nt++) {
                int bbx = (ks * 8 + tig) * BX_STRIDE + nt * 8 + gid;
                mma_tf32(s[nt], a, __float_as_uint(bsm2[bbx]),
                         __float_as_uint(bsm2[bbx + 4 * BX_STRIDE]));
            }
        }
    }
    int o0 = mt * 128 + warp * 16 + gid, o1 = o0 + 8;
    float bp0 = bproj[o0], bp1 = bproj[o1];
#pragma unroll
    for (int nt = 0; nt < 8; nt++) {
        int n = n0 + nt * 8 + 2 * tig;
        *(float2*)&out[((size_t)(b * 256 + o0)) * NPIX + n] =
            make_float2(s[nt][0] + bp0, s[nt][1] + bp0);
        *(float2*)&out[((size_t)(b * 256 + o1)) * NPIX + n] =
            make_float2(s[nt][2] + bp1, s[nt][3] + bp1);
    }
}

// ---------------------------------------------------------------------------
// launch
// ---------------------------------------------------------------------------
extern "C" void kernel_launch(void* const* d_in, const int* in_sizes, int n_in,
                              void* d_out, int out_size) {
    const float* x     = (const float*)d_in[0];
    const float* rgb   = (const float*)d_in[1];
    const float* wq    = (const float*)d_in[2];
    const float* bq    = (const float*)d_in[3];
    const float* wk    = (const float*)d_in[4];
    const float* bk    = (const float*)d_in[5];
    const float* wv    = (const float*)d_in[6];
    const float* bv    = (const float*)d_in[7];
    const float* wproj = (const float*)d_in[8];
    const float* bproj = (const float*)d_in[9];
    const float* c1w   = (const float*)d_in[10];
    const float* c1b   = (const float*)d_in[11];
    const float* c2w   = (const float*)d_in[12];
    const float* c2b   = (const float*)d_in[13];
    const float* alpha = (const float*)d_in[26];

    FilmArgs fa;
    fa.w[0] = (const float*)d_in[14]; fa.b[0] = (const float*)d_in[15];
    fa.w[1] = (const float*)d_in[16]; fa.b[1] = (const float*)d_in[17];
    fa.w[2] = (const float*)d_in[18]; fa.b[2] = (const float*)d_in[19];
    fa.w[3] = (const float*)d_in[20]; fa.b[3] = (const float*)d_in[21];
    fa.w[4] = (const float*)d_in[22]; fa.b[4] = (const float*)d_in[23];
    fa.w[5] = (const float*)d_in[24]; fa.b[5] = (const float*)d_in[25];

    static bool attr_done = false;
    if (!attr_done) {
        cudaFuncSetAttribute(k_attn, cudaFuncAttributeMaxDynamicSharedMemorySize, ATTN_SMEM);
        attr_done = true;
    }

    k_prep<<<2560, 256>>>(wq, wk, wv, wproj, x);
    k_lumabias<<<BSZ, 256>>>(rgb, alpha);
    k_conv1<<<dim3(HID, BSZ), 256>>>(c1w, c1b);
    k_conv2mean<<<dim3(HID / 4, BSZ, 3), dim3(16, 16)>>>(c2w, c2b);
    k_film<<<dim3(6, BSZ), 256>>>(fa);
    k_qkv<<<dim3(36, 2, 12), 256>>>(bq, bk, bv);
    k_attn<<<dim3(18, 32), 256, ATTN_SMEM>>>();
    k_proj<<<dim3(36, 2, 4), 256>>>(bproj, (float*)d_out);
}